// round 1
// baseline (speedup 1.0000x reference)
#include <cuda_runtime.h>
#include <math.h>

#define Mn 100
#define Cn 30
#define Dn 300
#define Kn 3
#define MC (Mn*Cn)          // 3000
#define ESTRIDE 301         // padded shared row stride (301 % 32 = 13, odd -> conflict-free)

// ---------------- scratch (device globals; no allocation allowed) ----------------
__device__ float g_f  [Mn*Dn];            // f[m,d]
__device__ float g_g  [Mn*Dn];            // g[m,d] = sum_e B[d,e] f[m,e]
__device__ float g_psi[MC];               // psi[m,c]
__device__ float g_h  [Kn*Mn*Dn];         // h[k,i,e] = sum_d f[i,d] D[k,d,e]
__device__ float g_a  [Mn*Mn*Kn];         // a[i,j,k]
__device__ float g_rk [Kn*MC*Dn];         // rk[k, j*30+q, e] = sum_d ent[j,q,d] R[k,d,e]   (10.8 MB)
__device__ float g_phi[Mn*Mn*Cn*Cn];      // phi[i,j,q,p]  (36 MB)  NOTE q-major then p
__device__ float g_mbar[2][Mn*Mn*Cn];     // double-buffered messages  mbar[i,j,c]
__device__ float g_stot[MC];              // stot[i,c] = sum_j mbar[j,i,c]

// ---------------- init ----------------
__global__ void k_zero() {
    int t = blockIdx.x * blockDim.x + threadIdx.x;
    if (t < Mn*Mn*Cn) g_mbar[0][t] = 0.f;
}

// ---------------- f = tanh(fmc_in @ W + b) ----------------
__global__ void k_f(const float* __restrict__ fin, const float* __restrict__ W,
                    const float* __restrict__ b) {
    __shared__ float s[3*Dn];
    int m = blockIdx.x;
    for (int t = threadIdx.x; t < 3*Dn; t += blockDim.x) s[t] = fin[m*3*Dn + t];
    __syncthreads();
    int d = threadIdx.x;
    if (d < Dn) {
        float acc = b[d];
        #pragma unroll 4
        for (int k = 0; k < 3*Dn; ++k) acc = fmaf(s[k], W[k*Dn + d], acc);
        g_f[m*Dn + d] = tanhf(acc);
    }
}

// ---------------- g[m,d] = dot(f[m,:], B[d,:]) (warp per (m,d)) ----------------
__global__ void k_g(const float* __restrict__ Bm) {
    int m = blockIdx.x;
    int w = threadIdx.x >> 5, lane = threadIdx.x & 31;
    int d = blockIdx.y * 4 + w;
    if (d >= Dn) return;
    float acc = 0.f;
    for (int e = lane; e < Dn; e += 32)
        acc = fmaf(g_f[m*Dn + e], Bm[d*Dn + e], acc);
    #pragma unroll
    for (int o = 16; o; o >>= 1) acc += __shfl_down_sync(0xffffffffu, acc, o);
    if (!lane) g_g[m*Dn + d] = acc;
}

// ---------------- psi[m,c] = dot(ent[m,c,:], g[m,:]) (warp per (m,c)) ----------------
__global__ void k_psi(const float* __restrict__ ent) {
    int m = blockIdx.x;
    int c = threadIdx.x >> 5, lane = threadIdx.x & 31;
    if (c >= Cn) return;
    float acc = 0.f;
    const float* er = ent + (m*Cn + c)*Dn;
    const float* gr = g_g + m*Dn;
    for (int d = lane; d < Dn; d += 32) acc = fmaf(er[d], gr[d], acc);
    #pragma unroll
    for (int o = 16; o; o >>= 1) acc += __shfl_down_sync(0xffffffffu, acc, o);
    if (!lane) g_psi[m*Cn + c] = acc;
}

// ---------------- h[k,i,e] = sum_d f[i,d] D[k,d,e] ----------------
__global__ void k_h(const float* __restrict__ Dm) {
    __shared__ float sf[Dn];
    int i = blockIdx.x, k = blockIdx.y;
    for (int t = threadIdx.x; t < Dn; t += blockDim.x) sf[t] = g_f[i*Dn + t];
    __syncthreads();
    int e = threadIdx.x;
    if (e < Dn) {
        float acc = 0.f;
        const float* Dk = Dm + (size_t)k*Dn*Dn;
        #pragma unroll 4
        for (int d = 0; d < Dn; ++d) acc = fmaf(sf[d], Dk[d*Dn + e], acc);
        g_h[(k*Mn + i)*Dn + e] = acc;
    }
}

// ---------------- s[i,j,k] and a = softmax_k ----------------
__global__ void k_a() {
    int j = blockIdx.x, i = blockIdx.y;
    int k = threadIdx.x >> 5, lane = threadIdx.x & 31;
    __shared__ float sv[Kn];
    float acc = 0.f;
    const float* hr = g_h + (k*Mn + i)*Dn;
    const float* fr = g_f + j*Dn;
    for (int e = lane; e < Dn; e += 32) acc = fmaf(hr[e], fr[e], acc);
    #pragma unroll
    for (int o = 16; o; o >>= 1) acc += __shfl_down_sync(0xffffffffu, acc, o);
    if (!lane) sv[k] = acc * (1.0f/17.320508075688772f);   // / sqrt(300)
    __syncthreads();
    if (threadIdx.x == 0) {
        float mx = fmaxf(sv[0], fmaxf(sv[1], sv[2]));
        float e0 = expf(sv[0]-mx), e1 = expf(sv[1]-mx), e2 = expf(sv[2]-mx);
        float inv = 1.0f / (e0+e1+e2);
        int base = (i*Mn + j)*Kn;
        g_a[base+0] = e0*inv; g_a[base+1] = e1*inv; g_a[base+2] = e2*inv;
    }
}

// ---------------- rk_k = ent_flat[3000,300] @ R_k[300,300] (tiled SGEMM) ----------------
__global__ void k_rk(const float* __restrict__ ent, const float* __restrict__ R) {
    const int BM = 64, BN = 64, BK = 8;
    int kk   = blockIdx.z;
    int row0 = blockIdx.y * BM;
    int col0 = blockIdx.x * BN;
    const float* A  = ent;
    const float* Bm = R + (size_t)kk*Dn*Dn;
    float*       Cm = g_rk + (size_t)kk*MC*Dn;
    __shared__ float As[BK][BM];
    __shared__ float Bs[BK][BN+1];
    int tid = threadIdx.x;
    int tn = tid & 15, tm = tid >> 4;
    float acc[4][4] = {};
    for (int d0 = 0; d0 < Dn; d0 += BK) {
        #pragma unroll
        for (int l = 0; l < 2; ++l) {
            int idx = tid + l*256;
            int mm = idx >> 3, dk = idx & 7;
            int gr = row0 + mm, gd = d0 + dk;
            As[dk][mm] = (gr < MC && gd < Dn) ? A[gr*Dn + gd] : 0.f;
        }
        #pragma unroll
        for (int l = 0; l < 2; ++l) {
            int idx = tid + l*256;
            int dk = idx >> 6, ee = idx & 63;
            int gd = d0 + dk, ge = col0 + ee;
            Bs[dk][ee] = (gd < Dn && ge < Dn) ? Bm[gd*Dn + ge] : 0.f;
        }
        __syncthreads();
        #pragma unroll
        for (int dk = 0; dk < BK; ++dk) {
            float ra[4], rb[4];
            #pragma unroll
            for (int x = 0; x < 4; ++x) ra[x] = As[dk][tm*4 + x];
            #pragma unroll
            for (int y = 0; y < 4; ++y) rb[y] = Bs[dk][tn*4 + y];
            #pragma unroll
            for (int x = 0; x < 4; ++x)
                #pragma unroll
                for (int y = 0; y < 4; ++y)
                    acc[x][y] = fmaf(ra[x], rb[y], acc[x][y]);
        }
        __syncthreads();
    }
    #pragma unroll
    for (int x = 0; x < 4; ++x) {
        int gr = row0 + tm*4 + x;
        if (gr < MC)
            #pragma unroll
            for (int y = 0; y < 4; ++y) {
                int ge = col0 + tn*4 + y;
                if (ge < Dn) Cm[gr*Dn + ge] = acc[x][y];
            }
    }
}

// ---------------- phi[i,j,q,p] = sum_e ent[i,p,e] * (sum_k a[i,j,k] rk[k,j*30+q,e]) ----------------
// block = (i, tile of 4 j's).  Shared: E_i [30x301] + wrk [30x301] = 72.24 KB (dynamic).
extern __shared__ float sh_phi[];
__global__ void k_phi(const float* __restrict__ ent) {
    float* Esh = sh_phi;
    float* Wsh = sh_phi + Cn*ESTRIDE;
    int i  = blockIdx.x;
    int jt = blockIdx.y;
    for (int t = threadIdx.x; t < Cn*Dn; t += blockDim.x) {
        int p = t / Dn, e = t - p*Dn;
        Esh[p*ESTRIDE + e] = ent[(i*Cn + p)*Dn + e];
    }
    int tp = threadIdx.x / 10, tq = threadIdx.x % 10;  // valid when tid < 100
    for (int jj = 0; jj < 4; ++jj) {
        int j = jt*4 + jj;
        float a0 = g_a[(i*Mn + j)*Kn + 0];
        float a1 = g_a[(i*Mn + j)*Kn + 1];
        float a2 = g_a[(i*Mn + j)*Kn + 2];
        __syncthreads();   // protect Wsh readers from previous j (and orders Esh on jj==0)
        for (int t = threadIdx.x; t < Cn*Dn; t += blockDim.x) {
            int q = t / Dn, e = t - q*Dn;
            int r = (j*Cn + q)*Dn + e;
            float v = a0*g_rk[r] + a1*g_rk[MC*Dn + r] + a2*g_rk[2*MC*Dn + r];
            Wsh[q*ESTRIDE + e] = v;
        }
        __syncthreads();
        if (threadIdx.x < 100) {
            int p0 = tp*3, q0 = tq*3;
            const float *x0p = Esh + p0*ESTRIDE, *x1p = x0p + ESTRIDE, *x2p = x0p + 2*ESTRIDE;
            const float *y0p = Wsh + q0*ESTRIDE, *y1p = y0p + ESTRIDE, *y2p = y0p + 2*ESTRIDE;
            float a00=0,a01=0,a02=0,a10=0,a11=0,a12=0,a20=0,a21=0,a22=0;
            #pragma unroll 5
            for (int e = 0; e < Dn; ++e) {
                float x0 = x0p[e], x1 = x1p[e], x2 = x2p[e];
                float y0 = y0p[e], y1 = y1p[e], y2 = y2p[e];
                a00 = fmaf(x0,y0,a00); a01 = fmaf(x0,y1,a01); a02 = fmaf(x0,y2,a02);
                a10 = fmaf(x1,y0,a10); a11 = fmaf(x1,y1,a11); a12 = fmaf(x1,y2,a12);
                a20 = fmaf(x2,y0,a20); a21 = fmaf(x2,y1,a21); a22 = fmaf(x2,y2,a22);
            }
            int base = (i*Mn + j)*Cn;   // phi[i,j,q,p] = g_phi[(base+q)*Cn + p]
            g_phi[(base+q0  )*Cn + p0  ] = a00;
            g_phi[(base+q0+1)*Cn + p0  ] = a01;
            g_phi[(base+q0+2)*Cn + p0  ] = a02;
            g_phi[(base+q0  )*Cn + p0+1] = a10;
            g_phi[(base+q0+1)*Cn + p0+1] = a11;
            g_phi[(base+q0+2)*Cn + p0+1] = a12;
            g_phi[(base+q0  )*Cn + p0+2] = a20;
            g_phi[(base+q0+1)*Cn + p0+2] = a21;
            g_phi[(base+q0+2)*Cn + p0+2] = a22;
        }
    }
}

// ---------------- per-iteration: stot[i,c] = sum_j mbar[j,i,c] ----------------
__global__ void k_stot(int src) {
    int t = blockIdx.x * blockDim.x + threadIdx.x;
    if (t >= MC) return;
    int i = t / Cn, p = t - i*Cn;
    const float* mb = g_mbar[src];
    float s = 0.f;
    for (int j = 0; j < Mn; ++j) s += mb[(j*Mn + i)*Cn + p];
    g_stot[t] = s;
}

// ---------------- LBP update for (i,j) ----------------
// vals[p,q] = psi[i,p] + stot[i,p] - mbar[j,i,p] + phi[i,j,p,q]
// mval[q]   = max(0, max_p vals);  new = log(0.5*exp(old) + 0.5*softmax_q(mval))
__global__ void k_lbp(int src) {
    int j = blockIdx.x, i = blockIdx.y;
    const float* mbold = g_mbar[src];
    float*       mbnew = g_mbar[src ^ 1];
    __shared__ float basep[Cn];
    __shared__ float smv[Cn];
    int tx = threadIdx.x, ty = threadIdx.y;
    int tid = ty*32 + tx;
    if (tid < Cn)
        basep[tid] = g_psi[i*Cn + tid] + g_stot[i*Cn + tid] - mbold[(j*Mn + i)*Cn + tid];
    __syncthreads();
    int q = ty;
    float v = -1e30f;
    if (tx < Cn) v = basep[tx] + g_phi[((i*Mn + j)*Cn + q)*Cn + tx];
    #pragma unroll
    for (int o = 16; o; o >>= 1) v = fmaxf(v, __shfl_down_sync(0xffffffffu, v, o));
    if (tx == 0) smv[q] = fmaxf(0.f, v);
    __syncthreads();
    if (ty == 0) {
        float mv = (tx < Cn) ? smv[tx] : -1e30f;
        float mx = mv;
        #pragma unroll
        for (int o = 16; o; o >>= 1) mx = fmaxf(mx, __shfl_xor_sync(0xffffffffu, mx, o));
        float ex = (tx < Cn) ? expf(mv - mx) : 0.f;
        float s = ex;
        #pragma unroll
        for (int o = 16; o; o >>= 1) s += __shfl_xor_sync(0xffffffffu, s, o);
        if (tx < Cn) {
            float soft = ex / s;
            float oldv = mbold[(i*Mn + j)*Cn + tx];
            mbnew[(i*Mn + j)*Cn + tx] = logf(0.5f*expf(oldv) + 0.5f*soft);
        }
    }
}

// ---------------- final: out[i,q] = softmax_q(psi + colsum - diag) ----------------
__global__ void k_fin(float* __restrict__ out) {
    int i = blockIdx.x, q = threadIdx.x;
    const float* mb = g_mbar[0];   // after 10 iterations result sits in buffer 0
    float u = -1e30f;
    if (q < Cn) {
        float s = g_psi[i*Cn + q];
        for (int j = 0; j < Mn; ++j) s += mb[(j*Mn + i)*Cn + q];
        s -= mb[(i*Mn + i)*Cn + q];
        u = s;
    }
    float mx = u;
    #pragma unroll
    for (int o = 16; o; o >>= 1) mx = fmaxf(mx, __shfl_xor_sync(0xffffffffu, mx, o));
    float ex = (q < Cn) ? expf(u - mx) : 0.f;
    float s = ex;
    #pragma unroll
    for (int o = 16; o; o >>= 1) s += __shfl_xor_sync(0xffffffffu, s, o);
    if (q < Cn) out[i*Cn + q] = ex / s;
}

// ---------------- launch ----------------
extern "C" void kernel_launch(void* const* d_in, const int* in_sizes, int n_in,
                              void* d_out, int out_size) {
    (void)in_sizes; (void)n_in; (void)out_size;
    const float* ent = (const float*)d_in[0];
    const float* fin = (const float*)d_in[1];
    const float* W   = (const float*)d_in[2];
    const float* b   = (const float*)d_in[3];
    const float* Bm  = (const float*)d_in[4];
    const float* R   = (const float*)d_in[5];
    const float* Dm  = (const float*)d_in[6];
    float* out = (float*)d_out;

    static const int PHI_SHMEM = 2 * Cn * ESTRIDE * (int)sizeof(float);  // 72240 B
    cudaFuncSetAttribute(k_phi, cudaFuncAttributeMaxDynamicSharedMemorySize, PHI_SHMEM);

    k_zero<<<(Mn*Mn*Cn + 255)/256, 256>>>();
    k_f  <<<Mn, 300>>>(fin, W, b);
    k_g  <<<dim3(Mn, 75), 128>>>(Bm);
    k_psi<<<Mn, 960>>>(ent);
    k_h  <<<dim3(Mn, Kn), 300>>>(Dm);
    k_a  <<<dim3(Mn, Mn), 96>>>();
    k_rk <<<dim3(5, 47, Kn), 256>>>(ent, R);
    k_phi<<<dim3(Mn, 25), 256, PHI_SHMEM>>>(ent);

    for (int t = 0; t < 10; ++t) {
        int src = t & 1;
        k_stot<<<(MC + 127)/128, 128>>>(src);
        k_lbp <<<dim3(Mn, Mn), dim3(32, Cn)>>>(src);
    }
    k_fin<<<Mn, 32>>>(out);
}

// round 2
// speedup vs baseline: 1.2644x; 1.2644x over previous
#include <cuda_runtime.h>
#include <math.h>

#define Mn 100
#define Cn 30
#define Dn 300
#define Kn 3
#define MC 3000            // Mn*Cn
#define D4 75              // Dn/4 (float4 per row)
#define NG 6               // j-groups per phi block
#define WS4 757            // padded float4 stride per group (30*25 + 7; 757 mod 8 = 5 -> bank-phase shift)
#define ECH 25             // float4 per e-chunk (100 floats)
#define PHI_THREADS (NG*36)   // 216

// ---------------- scratch (device globals; no allocation allowed) ----------------
__device__ __align__(16) float g_f  [Mn*Dn];
__device__ __align__(16) float g_g  [Mn*Dn];
__device__             float g_psi[MC];
__device__ __align__(16) float g_h  [Kn*Mn*Dn];
__device__             float g_a  [Mn*Mn*Kn];
__device__ __align__(16) float g_rk [Kn*MC*Dn];       // rk[k, j*30+q, e]  (10.8 MB)
__device__ __align__(16) float g_phi[Mn*Mn*Cn*Cn];    // phi[i,j,q,p]      (36 MB)
__device__             float g_mbar[2][Mn*Mn*Cn];
__device__             float g_stot[11][MC];          // per-iteration column sums

// ---------------- init: zero mbar[0] and all stot buffers ----------------
__global__ void k_zero() {
    int t = blockIdx.x * blockDim.x + threadIdx.x;
    if (t < Mn*Mn*Cn) g_mbar[0][t] = 0.f;
    if (t < 11*MC)    (&g_stot[0][0])[t] = 0.f;
}

// ---------------- f = tanh(fmc_in @ W + b), 4 rows per block ----------------
__global__ void k_f(const float* __restrict__ fin, const float* __restrict__ W,
                    const float* __restrict__ b) {
    __shared__ float s[4*3*Dn];
    int m0 = blockIdx.x * 4;
    for (int t = threadIdx.x; t < 4*3*Dn; t += 300) s[t] = fin[m0*3*Dn + t];
    __syncthreads();
    int d = threadIdx.x;   // 0..299
    float bb = b[d];
    float a0 = bb, a1 = bb, a2 = bb, a3 = bb;
    for (int k = 0; k < 3*Dn; ++k) {
        float w = W[k*Dn + d];
        a0 = fmaf(s[k],          w, a0);
        a1 = fmaf(s[900 + k],    w, a1);
        a2 = fmaf(s[1800 + k],   w, a2);
        a3 = fmaf(s[2700 + k],   w, a3);
    }
    g_f[(m0+0)*Dn + d] = tanhf(a0);
    g_f[(m0+1)*Dn + d] = tanhf(a1);
    g_f[(m0+2)*Dn + d] = tanhf(a2);
    g_f[(m0+3)*Dn + d] = tanhf(a3);
}

// ---------------- g[m,d] = dot(f[m,:], B[d,:]) ----------------
__global__ void k_g(const float* __restrict__ Bm) {
    int m = blockIdx.x;
    int w = threadIdx.x >> 5, lane = threadIdx.x & 31;
    int d = blockIdx.y * 4 + w;
    if (d >= Dn) return;
    float acc = 0.f;
    for (int e = lane; e < Dn; e += 32)
        acc = fmaf(g_f[m*Dn + e], Bm[d*Dn + e], acc);
    #pragma unroll
    for (int o = 16; o; o >>= 1) acc += __shfl_down_sync(0xffffffffu, acc, o);
    if (!lane) g_g[m*Dn + d] = acc;
}

// ---------------- psi[m,c] = dot(ent[m,c,:], g[m,:]) ----------------
__global__ void k_psi(const float* __restrict__ ent) {
    int m = blockIdx.x;
    int c = threadIdx.x >> 5, lane = threadIdx.x & 31;
    if (c >= Cn) return;
    float acc = 0.f;
    const float* er = ent + (m*Cn + c)*Dn;
    const float* gr = g_g + m*Dn;
    for (int d = lane; d < Dn; d += 32) acc = fmaf(er[d], gr[d], acc);
    #pragma unroll
    for (int o = 16; o; o >>= 1) acc += __shfl_down_sync(0xffffffffu, acc, o);
    if (!lane) g_psi[m*Cn + c] = acc;
}

// ---------------- h[k,i,e] = sum_d f[i,d] D[k,d,e], 4 i per block ----------------
__global__ void k_h(const float* __restrict__ Dm) {
    __shared__ float sf[4*Dn];
    int i0 = blockIdx.x * 4, k = blockIdx.y;
    for (int t = threadIdx.x; t < 4*Dn; t += 300) sf[t] = g_f[i0*Dn + t];
    __syncthreads();
    int e = threadIdx.x;
    const float* Dk = Dm + (size_t)k*Dn*Dn;
    float a0=0,a1=0,a2=0,a3=0;
    for (int d = 0; d < Dn; ++d) {
        float w = Dk[d*Dn + e];
        a0 = fmaf(sf[d],       w, a0);
        a1 = fmaf(sf[300 + d], w, a1);
        a2 = fmaf(sf[600 + d], w, a2);
        a3 = fmaf(sf[900 + d], w, a3);
    }
    g_h[(k*Mn + i0+0)*Dn + e] = a0;
    g_h[(k*Mn + i0+1)*Dn + e] = a1;
    g_h[(k*Mn + i0+2)*Dn + e] = a2;
    g_h[(k*Mn + i0+3)*Dn + e] = a3;
}

// ---------------- a[i,j,:] = softmax_k( h[k,i,:].f[j,:] / sqrt(d) ) ----------------
__global__ void k_a() {
    int j = blockIdx.x, i = blockIdx.y;
    int k = threadIdx.x >> 5, lane = threadIdx.x & 31;
    __shared__ float sv[Kn];
    float acc = 0.f;
    const float* hr = g_h + (k*Mn + i)*Dn;
    const float* fr = g_f + j*Dn;
    for (int e = lane; e < Dn; e += 32) acc = fmaf(hr[e], fr[e], acc);
    #pragma unroll
    for (int o = 16; o; o >>= 1) acc += __shfl_down_sync(0xffffffffu, acc, o);
    if (!lane) sv[k] = acc * (1.0f/17.320508075688772f);
    __syncthreads();
    if (threadIdx.x == 0) {
        float mx = fmaxf(sv[0], fmaxf(sv[1], sv[2]));
        float e0 = expf(sv[0]-mx), e1 = expf(sv[1]-mx), e2 = expf(sv[2]-mx);
        float inv = 1.0f / (e0+e1+e2);
        int base = (i*Mn + j)*Kn;
        g_a[base+0] = e0*inv; g_a[base+1] = e1*inv; g_a[base+2] = e2*inv;
    }
}

// ---------------- rk_k = ent_flat[3000,300] @ R_k[300,300] ----------------
__global__ void k_rk(const float* __restrict__ ent, const float* __restrict__ R) {
    const int BM = 64, BN = 64, BK = 8;
    int kk   = blockIdx.z;
    int row0 = blockIdx.y * BM;
    int col0 = blockIdx.x * BN;
    const float* A  = ent;
    const float* Bm = R + (size_t)kk*Dn*Dn;
    float*       Cm = g_rk + (size_t)kk*MC*Dn;
    __shared__ float As[BK][BM];
    __shared__ float Bs[BK][BN+1];
    int tid = threadIdx.x;
    int tn = tid & 15, tm = tid >> 4;
    float acc[4][4] = {};
    for (int d0 = 0; d0 < Dn; d0 += BK) {
        #pragma unroll
        for (int l = 0; l < 2; ++l) {
            int idx = tid + l*256;
            int mm = idx >> 3, dk = idx & 7;
            int gr = row0 + mm, gd = d0 + dk;
            As[dk][mm] = (gr < MC && gd < Dn) ? A[gr*Dn + gd] : 0.f;
        }
        #pragma unroll
        for (int l = 0; l < 2; ++l) {
            int idx = tid + l*256;
            int dk = idx >> 6, ee = idx & 63;
            int gd = d0 + dk, ge = col0 + ee;
            Bs[dk][ee] = (gd < Dn && ge < Dn) ? Bm[gd*Dn + ge] : 0.f;
        }
        __syncthreads();
        #pragma unroll
        for (int dk = 0; dk < BK; ++dk) {
            float ra[4], rb[4];
            #pragma unroll
            for (int x = 0; x < 4; ++x) ra[x] = As[dk][tm*4 + x];
            #pragma unroll
            for (int y = 0; y < 4; ++y) rb[y] = Bs[dk][tn*4 + y];
            #pragma unroll
            for (int x = 0; x < 4; ++x)
                #pragma unroll
                for (int y = 0; y < 4; ++y)
                    acc[x][y] = fmaf(ra[x], rb[y], acc[x][y]);
        }
        __syncthreads();
    }
    #pragma unroll
    for (int x = 0; x < 4; ++x) {
        int gr = row0 + tm*4 + x;
        if (gr < MC)
            #pragma unroll
            for (int y = 0; y < 4; ++y) {
                int ge = col0 + tn*4 + y;
                if (ge < Dn) Cm[gr*Dn + ge] = acc[x][y];
            }
    }
}

// ---------------- phi: block = (i, 6 j's), 5x5 register tiles, e-chunked smem ----------------
// Esh: 2250 float4 (E_i full). Wsh: NG groups, stride WS4 float4, each 30 rows x 25 float4.
extern __shared__ float4 sh4[];
__global__ __launch_bounds__(PHI_THREADS) void k_phi(const float* __restrict__ ent) {
    float4* E4 = sh4;                 // [p*75 + e4]
    float4* W4 = sh4 + 2250;          // [g*WS4 + q*25 + e4]
    __shared__ float ash[NG][3];
    int i  = blockIdx.x;
    int j0 = blockIdx.y * NG;
    int tid = threadIdx.x;
    int g = tid / 36, w = tid % 36;
    int j = j0 + g;
    bool jv = (j < Mn);

    const float4* entp = (const float4*)ent;
    for (int t = tid; t < 2250; t += PHI_THREADS)
        E4[t] = entp[i*2250 + t];
    if (tid < NG*3) {
        int gg = tid/3, kk2 = tid%3;
        int jj2 = j0 + gg;
        ash[gg][kk2] = (jj2 < Mn) ? g_a[(i*Mn + jj2)*Kn + kk2] : 0.f;
    }

    int tp = w / 6, tq = w % 6;
    int p0 = tp*5, q0 = tq*5;
    float acc[5][5] = {};
    const float4* rkp = (const float4*)g_rk;

    for (int ch = 0; ch < 3; ++ch) {
        __syncthreads();   // Esh/ash ready (ch 0); Wsh readers done (ch>0)
        // weight fill: NG * 30 * 25 float4
        for (int t = tid; t < NG*750; t += PHI_THREADS) {
            int gg = t / 750, r = t % 750;
            int jj2 = j0 + gg;
            if (jj2 < Mn) {
                int q = r / 25, e4 = r % 25;
                int idx = (jj2*Cn + q)*D4 + ch*ECH + e4;
                float4 v0 = rkp[idx];
                float4 v1 = rkp[225000 + idx];
                float4 v2 = rkp[450000 + idx];
                float a0 = ash[gg][0], a1 = ash[gg][1], a2 = ash[gg][2];
                float4 o;
                o.x = a0*v0.x + a1*v1.x + a2*v2.x;
                o.y = a0*v0.y + a1*v1.y + a2*v2.y;
                o.z = a0*v0.z + a1*v1.z + a2*v2.z;
                o.w = a0*v0.w + a1*v1.w + a2*v2.w;
                W4[gg*WS4 + q*25 + e4] = o;
            }
        }
        __syncthreads();
        if (jv) {
            const float4* Wg = W4 + g*WS4;
            const float4* Eb = E4 + ch*ECH;
            #pragma unroll 2
            for (int e4 = 0; e4 < ECH; ++e4) {
                float4 xs[5], ys[5];
                #pragma unroll
                for (int r = 0; r < 5; ++r) xs[r] = Eb[(p0+r)*D4 + e4];
                #pragma unroll
                for (int c = 0; c < 5; ++c) ys[c] = Wg[(q0+c)*ECH + e4];
                #pragma unroll
                for (int r = 0; r < 5; ++r)
                    #pragma unroll
                    for (int c = 0; c < 5; ++c) {
                        acc[r][c] = fmaf(xs[r].x, ys[c].x, acc[r][c]);
                        acc[r][c] = fmaf(xs[r].y, ys[c].y, acc[r][c]);
                        acc[r][c] = fmaf(xs[r].z, ys[c].z, acc[r][c]);
                        acc[r][c] = fmaf(xs[r].w, ys[c].w, acc[r][c]);
                    }
            }
        }
    }
    if (jv) {
        int base = (i*Mn + j)*Cn;   // phi[i,j,q,p]
        #pragma unroll
        for (int c = 0; c < 5; ++c)
            #pragma unroll
            for (int r = 0; r < 5; ++r)
                g_phi[(base + q0 + c)*Cn + p0 + r] = acc[r][c];
    }
}

// ---------------- LBP iteration t: block = (i, 10 j's) ----------------
__global__ void k_lbp(int t) {
    int i  = blockIdx.y;
    int jt = blockIdx.x;
    int src = t & 1;
    const float* mbold = g_mbar[src];
    float*       mbnew = g_mbar[src ^ 1];
    const float* stot  = g_stot[t];
    float*       stotn = g_stot[t+1];
    __shared__ float base0[Cn], smv[Cn];
    int tx = threadIdx.x & 31, ty = threadIdx.x >> 5;   // ty = q (30 warps)
    if (threadIdx.x < Cn)
        base0[threadIdx.x] = g_psi[i*Cn + threadIdx.x] + stot[i*Cn + threadIdx.x];
    __syncthreads();
    for (int jj = 0; jj < 10; ++jj) {
        int j = jt*10 + jj;
        float v = -1e30f;
        if (tx < Cn)
            v = base0[tx] - mbold[(j*Mn + i)*Cn + tx]
              + g_phi[((i*Mn + j)*Cn + ty)*Cn + tx];
        #pragma unroll
        for (int o = 16; o; o >>= 1) v = fmaxf(v, __shfl_down_sync(0xffffffffu, v, o));
        if (tx == 0) smv[ty] = fmaxf(0.f, v);
        __syncthreads();
        if (ty == 0) {
            float mv = (tx < Cn) ? smv[tx] : -1e30f;
            float mx = mv;
            #pragma unroll
            for (int o = 16; o; o >>= 1) mx = fmaxf(mx, __shfl_xor_sync(0xffffffffu, mx, o));
            float ex = (tx < Cn) ? expf(mv - mx) : 0.f;
            float s = ex;
            #pragma unroll
            for (int o = 16; o; o >>= 1) s += __shfl_xor_sync(0xffffffffu, s, o);
            if (tx < Cn) {
                float soft = ex / s;
                float oldv = mbold[(i*Mn + j)*Cn + tx];
                float nv = logf(0.5f*expf(oldv) + 0.5f*soft);
                mbnew[(i*Mn + j)*Cn + tx] = nv;
                atomicAdd(&stotn[j*Cn + tx], nv);   // mb[i,j,c] contributes to stot of receiver j
            }
        }
        __syncthreads();
    }
}

// ---------------- final softmax ----------------
__global__ void k_fin(float* __restrict__ out) {
    int i = blockIdx.x, q = threadIdx.x;
    const float* mb = g_mbar[0];
    float u = -1e30f;
    if (q < Cn)
        u = g_psi[i*Cn + q] + g_stot[10][i*Cn + q] - mb[(i*Mn + i)*Cn + q];
    float mx = u;
    #pragma unroll
    for (int o = 16; o; o >>= 1) mx = fmaxf(mx, __shfl_xor_sync(0xffffffffu, mx, o));
    float ex = (q < Cn) ? expf(u - mx) : 0.f;
    float s = ex;
    #pragma unroll
    for (int o = 16; o; o >>= 1) s += __shfl_xor_sync(0xffffffffu, s, o);
    if (q < Cn) out[i*Cn + q] = ex / s;
}

// ---------------- launch ----------------
extern "C" void kernel_launch(void* const* d_in, const int* in_sizes, int n_in,
                              void* d_out, int out_size) {
    (void)in_sizes; (void)n_in; (void)out_size;
    const float* ent = (const float*)d_in[0];
    const float* fin = (const float*)d_in[1];
    const float* W   = (const float*)d_in[2];
    const float* b   = (const float*)d_in[3];
    const float* Bm  = (const float*)d_in[4];
    const float* R   = (const float*)d_in[5];
    const float* Dm  = (const float*)d_in[6];
    float* out = (float*)d_out;

    const int PHI_SHMEM = (2250 + NG*WS4) * 16;   // 108,672 B -> 2 blocks/SM
    cudaFuncSetAttribute(k_phi, cudaFuncAttributeMaxDynamicSharedMemorySize, PHI_SHMEM);

    k_zero<<<(Mn*Mn*Cn + 255)/256, 256>>>();
    k_f  <<<25, 300>>>(fin, W, b);
    k_g  <<<dim3(Mn, 75), 128>>>(Bm);
    k_psi<<<Mn, 960>>>(ent);
    k_h  <<<dim3(25, Kn), 300>>>(Dm);
    k_a  <<<dim3(Mn, Mn), 96>>>();
    k_rk <<<dim3(5, 47, Kn), 256>>>(ent, R);
    k_phi<<<dim3(Mn, 17), PHI_THREADS, PHI_SHMEM>>>(ent);

    for (int t = 0; t < 10; ++t)
        k_lbp<<<dim3(10, Mn), 960>>>(t);
    k_fin<<<Mn, 32>>>(out);
}

// round 4
// speedup vs baseline: 1.3095x; 1.0356x over previous
#include <cuda_runtime.h>
#include <cuda_bf16.h>
#include <math.h>
#include <stdint.h>

#define Mn 100
#define Cn 30
#define Dn 300
#define Kn 3
#define MC 3000
#define MP 3072            // padded GEMM dim
#define KP 320             // padded K
#define R4U 40             // uint4 per padded row (320*2/16)

// ---------------- scratch ----------------
__device__ __align__(16) float g_f  [Mn*Dn];
__device__ __align__(16) float g_g  [Mn*Dn];
__device__             float g_psi[MC];
__device__ __align__(16) float g_h  [Kn*Mn*Dn];
__device__             float g_a  [Mn*Mn*Kn];
__device__ __align__(16) __nv_bfloat16 g_entH[MP*KP];
__device__ __align__(16) __nv_bfloat16 g_entL[MP*KP];
__device__ __align__(16) __nv_bfloat16 g_rkH [Kn*MP*KP];
__device__ __align__(16) __nv_bfloat16 g_rkL [Kn*MP*KP];
__device__ __align__(16) float g_phi[Mn*Mn*Cn*Cn];       // phi[i,j,q,p]
__device__             float g_mbar[2][Mn*Mn*Cn];
__device__             float g_stot[11][MC];

// ---------------- init: zero mbar/stot + pad regions of split arrays ----------------
__global__ void k_zero() {
    int t = blockIdx.x * blockDim.x + threadIdx.x;
    if (t < Mn*Mn*Cn) g_mbar[0][t] = 0.f;
    if (t < 11*MC)    (&g_stot[0][0])[t] = 0.f;
    if (t < Kn*MP*KP) {
        int r = (t / KP) % MP, c = t % KP;
        if (r >= MC || c >= Dn) {
            g_rkH[t] = __float2bfloat16(0.f);
            g_rkL[t] = __float2bfloat16(0.f);
        }
    }
}

// ---------------- f = tanh(fmc_in @ W + b) ----------------
__global__ void k_f(const float* __restrict__ fin, const float* __restrict__ W,
                    const float* __restrict__ b) {
    __shared__ float s[4*3*Dn];
    int m0 = blockIdx.x * 4;
    for (int t = threadIdx.x; t < 4*3*Dn; t += 300) s[t] = fin[m0*3*Dn + t];
    __syncthreads();
    int d = threadIdx.x;
    float bb = b[d];
    float a0 = bb, a1 = bb, a2 = bb, a3 = bb;
    for (int k = 0; k < 3*Dn; ++k) {
        float w = W[k*Dn + d];
        a0 = fmaf(s[k],        w, a0);
        a1 = fmaf(s[900 + k],  w, a1);
        a2 = fmaf(s[1800 + k], w, a2);
        a3 = fmaf(s[2700 + k], w, a3);
    }
    g_f[(m0+0)*Dn + d] = tanhf(a0);
    g_f[(m0+1)*Dn + d] = tanhf(a1);
    g_f[(m0+2)*Dn + d] = tanhf(a2);
    g_f[(m0+3)*Dn + d] = tanhf(a3);
}

// ---------------- g[m,d] = dot(f[m,:], B[d,:]) ----------------
__global__ void k_g(const float* __restrict__ Bm) {
    int m = blockIdx.x;
    int w = threadIdx.x >> 5, lane = threadIdx.x & 31;
    int d = blockIdx.y * 4 + w;
    if (d >= Dn) return;
    float acc = 0.f;
    for (int e = lane; e < Dn; e += 32)
        acc = fmaf(g_f[m*Dn + e], Bm[d*Dn + e], acc);
    #pragma unroll
    for (int o = 16; o; o >>= 1) acc += __shfl_down_sync(0xffffffffu, acc, o);
    if (!lane) g_g[m*Dn + d] = acc;
}

// ---------------- psi ----------------
__global__ void k_psi(const float* __restrict__ ent) {
    int m = blockIdx.x;
    int c = threadIdx.x >> 5, lane = threadIdx.x & 31;
    if (c >= Cn) return;
    float acc = 0.f;
    const float* er = ent + (m*Cn + c)*Dn;
    const float* gr = g_g + m*Dn;
    for (int d = lane; d < Dn; d += 32) acc = fmaf(er[d], gr[d], acc);
    #pragma unroll
    for (int o = 16; o; o >>= 1) acc += __shfl_down_sync(0xffffffffu, acc, o);
    if (!lane) g_psi[m*Cn + c] = acc;
}

// ---------------- h ----------------
__global__ void k_h(const float* __restrict__ Dm) {
    __shared__ float sf[4*Dn];
    int i0 = blockIdx.x * 4, k = blockIdx.y;
    for (int t = threadIdx.x; t < 4*Dn; t += 300) sf[t] = g_f[i0*Dn + t];
    __syncthreads();
    int e = threadIdx.x;
    const float* Dk = Dm + (size_t)k*Dn*Dn;
    float a0=0,a1=0,a2=0,a3=0;
    for (int d = 0; d < Dn; ++d) {
        float w = Dk[d*Dn + e];
        a0 = fmaf(sf[d],       w, a0);
        a1 = fmaf(sf[300 + d], w, a1);
        a2 = fmaf(sf[600 + d], w, a2);
        a3 = fmaf(sf[900 + d], w, a3);
    }
    g_h[(k*Mn + i0+0)*Dn + e] = a0;
    g_h[(k*Mn + i0+1)*Dn + e] = a1;
    g_h[(k*Mn + i0+2)*Dn + e] = a2;
    g_h[(k*Mn + i0+3)*Dn + e] = a3;
}

// ---------------- a[i,j,:] ----------------
__global__ void k_a2() {
    __shared__ float sh[Kn][Dn];
    int i = blockIdx.x;
    for (int t = threadIdx.x; t < Kn*Dn; t += 320) {
        int k = t / Dn, e = t - k*Dn;
        sh[k][e] = g_h[(k*Mn + i)*Dn + e];
    }
    __syncthreads();
    int w = threadIdx.x >> 5, lane = threadIdx.x & 31;
    for (int j = w; j < Mn; j += 10) {
        float fr[10];
        #pragma unroll
        for (int r = 0; r < 10; ++r) {
            int e = lane + 32*r;
            fr[r] = (e < Dn) ? g_f[j*Dn + e] : 0.f;
        }
        float sv[3];
        #pragma unroll
        for (int k = 0; k < 3; ++k) {
            float acc = 0.f;
            #pragma unroll
            for (int r = 0; r < 10; ++r) {
                int e = lane + 32*r;
                if (e < Dn) acc = fmaf(fr[r], sh[k][e], acc);
            }
            #pragma unroll
            for (int o = 16; o; o >>= 1) acc += __shfl_xor_sync(0xffffffffu, acc, o);
            sv[k] = acc * (1.0f/17.320508075688772f);
        }
        if (!lane) {
            float mx = fmaxf(sv[0], fmaxf(sv[1], sv[2]));
            float e0 = expf(sv[0]-mx), e1 = expf(sv[1]-mx), e2 = expf(sv[2]-mx);
            float inv = 1.0f / (e0+e1+e2);
            int base = (i*Mn + j)*Kn;
            g_a[base+0] = e0*inv; g_a[base+1] = e1*inv; g_a[base+2] = e2*inv;
        }
    }
}

// ---------------- rk_k = ent_flat @ R_k -> bf16 hi/lo padded [3072][320] ----------------
__global__ void k_rk(const float* __restrict__ ent, const float* __restrict__ R) {
    const int BM = 64, BN = 64, BK = 8;
    int kk   = blockIdx.z;
    int row0 = blockIdx.y * BM;
    int col0 = blockIdx.x * BN;
    const float* A  = ent;
    const float* Bm = R + (size_t)kk*Dn*Dn;
    __shared__ float As[BK][BM];
    __shared__ float Bs[BK][BN+1];
    int tid = threadIdx.x;
    int tn = tid & 15, tm = tid >> 4;
    float acc[4][4] = {};
    for (int d0 = 0; d0 < Dn; d0 += BK) {
        #pragma unroll
        for (int l = 0; l < 2; ++l) {
            int idx = tid + l*256;
            int mm = idx >> 3, dk = idx & 7;
            int gr = row0 + mm, gd = d0 + dk;
            As[dk][mm] = (gr < MC && gd < Dn) ? A[gr*Dn + gd] : 0.f;
        }
        #pragma unroll
        for (int l = 0; l < 2; ++l) {
            int idx = tid + l*256;
            int dk = idx >> 6, ee = idx & 63;
            int gd = d0 + dk, ge = col0 + ee;
            Bs[dk][ee] = (gd < Dn && ge < Dn) ? Bm[gd*Dn + ge] : 0.f;
        }
        __syncthreads();
        #pragma unroll
        for (int dk = 0; dk < BK; ++dk) {
            float ra[4], rb[4];
            #pragma unroll
            for (int x = 0; x < 4; ++x) ra[x] = As[dk][tm*4 + x];
            #pragma unroll
            for (int y = 0; y < 4; ++y) rb[y] = Bs[dk][tn*4 + y];
            #pragma unroll
            for (int x = 0; x < 4; ++x)
                #pragma unroll
                for (int y = 0; y < 4; ++y)
                    acc[x][y] = fmaf(ra[x], rb[y], acc[x][y]);
        }
        __syncthreads();
    }
    #pragma unroll
    for (int x = 0; x < 4; ++x) {
        int gr = row0 + tm*4 + x;
        if (gr < MC)
            #pragma unroll
            for (int y = 0; y < 4; ++y) {
                int ge = col0 + tn*4 + y;
                if (ge < Dn) {
                    float v = acc[x][y];
                    __nv_bfloat16 h = __float2bfloat16(v);
                    __nv_bfloat16 l = __float2bfloat16(v - __bfloat162float(h));
                    size_t o = (size_t)kk*MP*KP + (size_t)gr*KP + ge;
                    g_rkH[o] = h; g_rkL[o] = l;
                }
            }
    }
}

// ---------------- split ent -> bf16 hi/lo padded [3072][320] ----------------
__global__ void k_split(const float* __restrict__ ent) {
    int t = blockIdx.x * 256 + threadIdx.x;
    if (t >= MP*KP) return;
    int row = t / KP, col = t - row*KP;
    float v = (row < MC && col < Dn) ? ent[row*Dn + col] : 0.f;
    __nv_bfloat16 h = __float2bfloat16(v);
    __nv_bfloat16 l = __float2bfloat16(v - __bfloat162float(h));
    g_entH[t] = h; g_entL[t] = l;
}

// ---------------- phi via mma.sync bf16 hi/lo ----------------
__device__ __forceinline__ void mma16816(float* c, const uint32_t* a, const uint32_t* b) {
    asm volatile("mma.sync.aligned.m16n8k16.row.col.f32.bf16.bf16.f32 "
        "{%0,%1,%2,%3}, {%4,%5,%6,%7}, {%8,%9}, {%0,%1,%2,%3};"
        : "+f"(c[0]), "+f"(c[1]), "+f"(c[2]), "+f"(c[3])
        : "r"(a[0]), "r"(a[1]), "r"(a[2]), "r"(a[3]), "r"(b[0]), "r"(b[1]));
}

// CTA tile 128(m) x 64(n); 8 warps 4x2, warp tile 32x32; BK=64, K=320 (5 chunks)
// smem: Ah[128][72], Al[128][72], Bh[64][72], Bl[64][72] = 27648 bf16 = 55296 B
#define SM_AH 0
#define SM_AL 9216
#define SM_BH 18432
#define SM_BL 23040
extern __shared__ __nv_bfloat16 smg[];
__global__ __launch_bounds__(256, 2) void k_gemm() {
    __shared__ float s_a[6][4][3];
    int tid = threadIdx.x, lane = tid & 31, wid = tid >> 5;
    int m0 = blockIdx.y * 128, n0 = blockIdx.x * 64;
    int jb = m0 / 30, ib = n0 / 30;
    int wm = (wid & 3) * 32, wn = (wid >> 2) * 32;

    if (tid < 72) {
        int jl = tid / 12, rem = tid % 12, il = rem / 3, k = rem % 3;
        int jj = jb + jl, ii = ib + il;
        s_a[jl][il][k] = (jj < Mn && ii < Mn) ? g_a[(ii*Mn + jj)*Kn + k] : 0.f;
    }

    const uint4* AH = (const uint4*)g_rkH;
    const uint4* AL = (const uint4*)g_rkL;
    const uint4* BH = (const uint4*)g_entH;
    const uint4* BL = (const uint4*)g_entL;

    // per-thread fragment coordinates
    int fr = lane >> 2;            // 0..7
    int fk = (lane & 3) * 2;       // 0,2,4,6

    float accP[2][4][4];
    #pragma unroll
    for (int mi = 0; mi < 2; ++mi)
        #pragma unroll
        for (int ni = 0; ni < 4; ++ni)
            #pragma unroll
            for (int c = 0; c < 4; ++c) accP[mi][ni][c] = 0.f;

    for (int pl = 0; pl < 3; ++pl) {
        float accG[2][4][4];
        #pragma unroll
        for (int mi = 0; mi < 2; ++mi)
            #pragma unroll
            for (int ni = 0; ni < 4; ++ni)
                #pragma unroll
                for (int c = 0; c < 4; ++c) accG[mi][ni][c] = 0.f;

        for (int kc = 0; kc < 5; ++kc) {
            __syncthreads();
            // fill 3072 uint4: Ah 1024, Al 1024, Bh 512, Bl 512
            #pragma unroll
            for (int l = 0; l < 12; ++l) {
                int u = tid + l*256;
                uint4 v; int dst;
                if (u < 2048) {
                    int uu = u & 1023, r = uu >> 3, c = uu & 7;
                    size_t gi = (size_t)pl*(MP*R4U) + (size_t)(m0 + r)*R4U + kc*8 + c;
                    v = (u < 1024) ? AH[gi] : AL[gi];
                    dst = ((u < 1024) ? SM_AH : SM_AL) + r*72 + c*8;
                } else {
                    int uu = (u - 2048) & 511, r = uu >> 3, c = uu & 7;
                    size_t gi = (size_t)(n0 + r)*R4U + kc*8 + c;
                    v = (u < 2560) ? BH[gi] : BL[gi];
                    dst = ((u < 2560) ? SM_BH : SM_BL) + r*72 + c*8;
                }
                *(uint4*)&smg[dst] = v;
            }
            __syncthreads();
            #pragma unroll
            for (int ks = 0; ks < 4; ++ks) {
                int kk = ks*16 + fk;
                uint32_t ah[2][4], al[2][4], bh[4][2], bl[4][2];
                #pragma unroll
                for (int mi = 0; mi < 2; ++mi) {
                    int r = wm + mi*16 + fr;
                    ah[mi][0] = *(const uint32_t*)&smg[SM_AH + r*72 + kk];
                    ah[mi][1] = *(const uint32_t*)&smg[SM_AH + (r+8)*72 + kk];
                    ah[mi][2] = *(const uint32_t*)&smg[SM_AH + r*72 + kk + 8];
                    ah[mi][3] = *(const uint32_t*)&smg[SM_AH + (r+8)*72 + kk + 8];
                    al[mi][0] = *(const uint32_t*)&smg[SM_AL + r*72 + kk];
                    al[mi][1] = *(const uint32_t*)&smg[SM_AL + (r+8)*72 + kk];
                    al[mi][2] = *(const uint32_t*)&smg[SM_AL + r*72 + kk + 8];
                    al[mi][3] = *(const uint32_t*)&smg[SM_AL + (r+8)*72 + kk + 8];
                }
                #pragma unroll
                for (int ni = 0; ni < 4; ++ni) {
                    int r = wn + ni*8 + fr;
                    bh[ni][0] = *(const uint32_t*)&smg[SM_BH + r*72 + kk];
                    bh[ni][1] = *(const uint32_t*)&smg[SM_BH + r*72 + kk + 8];
                    bl[ni][0] = *(const uint32_t*)&smg[SM_BL + r*72 + kk];
                    bl[ni][1] = *(const uint32_t*)&smg[SM_BL + r*72 + kk + 8];
                }
                #pragma unroll
                for (int mi = 0; mi < 2; ++mi)
                    #pragma unroll
                    for (int ni = 0; ni < 4; ++ni) {
                        mma16816(accG[mi][ni], ah[mi], bh[ni]);
                        mma16816(accG[mi][ni], al[mi], bh[ni]);
                        mma16816(accG[mi][ni], ah[mi], bl[ni]);
                    }
            }
        }
        // fold plane into phi accumulator with a-weights
        #pragma unroll
        for (int mi = 0; mi < 2; ++mi) {
            #pragma unroll
            for (int ni = 0; ni < 4; ++ni) {
                int rm = m0 + wm + mi*16 + fr;
                int cn = n0 + wn + ni*8 + fk;
                #pragma unroll
                for (int c = 0; c < 4; ++c) {
                    int m = rm + (c >> 1)*8;
                    int n = cn + (c & 1);
                    if (m < MC && n < MC) {
                        int j = m / 30, i = n / 30;
                        accP[mi][ni][c] += s_a[j - jb][i - ib][pl] * accG[mi][ni][c];
                    }
                }
            }
        }
    }
    // write phi
    #pragma unroll
    for (int mi = 0; mi < 2; ++mi) {
        #pragma unroll
        for (int ni = 0; ni < 4; ++ni) {
            int rm = m0 + wm + mi*16 + fr;
            int cn = n0 + wn + ni*8 + fk;
            #pragma unroll
            for (int c = 0; c < 4; ++c) {
                int m = rm + (c >> 1)*8;
                int n = cn + (c & 1);
                if (m < MC && n < MC) {
                    int j = m / 30, q = m - j*30;
                    int i = n / 30, p = n - i*30;
                    g_phi[((i*Mn + j)*Cn + q)*Cn + p] = accP[mi][ni][c];
                }
            }
        }
    }
}

// ---------------- LBP iteration ----------------
__global__ void k_lbp(int t) {
    int i  = blockIdx.y;
    int jt = blockIdx.x;
    int src = t & 1;
    const float* mbold = g_mbar[src];
    float*       mbnew = g_mbar[src ^ 1];
    const float* stot  = g_stot[t];
    float*       stotn = g_stot[t+1];
    __shared__ float base0[Cn], smv[Cn];
    int tx = threadIdx.x & 31, ty = threadIdx.x >> 5;
    if (threadIdx.x < Cn)
        base0[threadIdx.x] = g_psi[i*Cn + threadIdx.x] + stot[i*Cn + threadIdx.x];
    __syncthreads();
    for (int jj = 0; jj < 10; ++jj) {
        int j = jt*10 + jj;
        float v = -1e30f;
        if (tx < Cn)
            v = base0[tx] - mbold[(j*Mn + i)*Cn + tx]
              + g_phi[((i*Mn + j)*Cn + ty)*Cn + tx];
        #pragma unroll
        for (int o = 16; o; o >>= 1) v = fmaxf(v, __shfl_down_sync(0xffffffffu, v, o));
        if (tx == 0) smv[ty] = fmaxf(0.f, v);
        __syncthreads();
        if (ty == 0) {
            float mv = (tx < Cn) ? smv[tx] : -1e30f;
            float mx = mv;
            #pragma unroll
            for (int o = 16; o; o >>= 1) mx = fmaxf(mx, __shfl_xor_sync(0xffffffffu, mx, o));
            float ex = (tx < Cn) ? expf(mv - mx) : 0.f;
            float s = ex;
            #pragma unroll
            for (int o = 16; o; o >>= 1) s += __shfl_xor_sync(0xffffffffu, s, o);
            if (tx < Cn) {
                float soft = ex / s;
                float oldv = mbold[(i*Mn + j)*Cn + tx];
                float nv = logf(0.5f*expf(oldv) + 0.5f*soft);
                mbnew[(i*Mn + j)*Cn + tx] = nv;
                atomicAdd(&stotn[j*Cn + tx], nv);
            }
        }
        __syncthreads();
    }
}

// ---------------- final ----------------
__global__ void k_fin(float* __restrict__ out) {
    int i = blockIdx.x, q = threadIdx.x;
    const float* mb = g_mbar[0];
    float u = -1e30f;
    if (q < Cn)
        u = g_psi[i*Cn + q] + g_stot[10][i*Cn + q] - mb[(i*Mn + i)*Cn + q];
    float mx = u;
    #pragma unroll
    for (int o = 16; o; o >>= 1) mx = fmaxf(mx, __shfl_xor_sync(0xffffffffu, mx, o));
    float ex = (q < Cn) ? expf(u - mx) : 0.f;
    float s = ex;
    #pragma unroll
    for (int o = 16; o; o >>= 1) s += __shfl_xor_sync(0xffffffffu, s, o);
    if (q < Cn) out[i*Cn + q] = ex / s;
}

// ---------------- launch ----------------
extern "C" void kernel_launch(void* const* d_in, const int* in_sizes, int n_in,
                              void* d_out, int out_size) {
    (void)in_sizes; (void)n_in; (void)out_size;
    const float* ent = (const float*)d_in[0];
    const float* fin = (const float*)d_in[1];
    const float* W   = (const float*)d_in[2];
    const float* b   = (const float*)d_in[3];
    const float* Bm  = (const float*)d_in[4];
    const float* R   = (const float*)d_in[5];
    const float* Dm  = (const float*)d_in[6];
    float* out = (float*)d_out;

    const int GEMM_SHMEM = 27648 * 2;   // 55296 B
    cudaFuncSetAttribute(k_gemm, cudaFuncAttributeMaxDynamicSharedMemorySize, GEMM_SHMEM);

    k_zero<<<(Kn*MP*KP + 255)/256, 256>>>();
    k_f  <<<25, 300>>>(fin, W, b);
    k_g  <<<dim3(Mn, 75), 128>>>(Bm);
    k_psi<<<Mn, 960>>>(ent);
    k_h  <<<dim3(25, Kn), 300>>>(Dm);
    k_a2 <<<Mn, 320>>>();
    k_rk <<<dim3(5, 47, Kn), 256>>>(ent, R);
    k_split<<<(MP*KP + 255)/256, 256>>>(ent);
    k_gemm<<<dim3(48, 24), 256, GEMM_SHMEM>>>();

    for (int t = 0; t < 10; ++t)
        k_lbp<<<dim3(10, Mn), 960>>>(t);
    k_fin<<<Mn, 32>>>(out);
}

// round 8
// speedup vs baseline: 1.9432x; 1.4840x over previous
#include <cuda_runtime.h>
#include <cuda_bf16.h>
#include <math.h>
#include <stdint.h>

#define Mn 100
#define Cn 30
#define Dn 300
#define Kn 3
#define MC 3000
#define MP 3072            // padded GEMM dim
#define KP 320             // padded K
#define R4U 40             // uint4 per padded row (320*2/16)

// ---------------- scratch ----------------
__device__ __align__(16) float g_f  [Mn*Dn];
__device__ __align__(16) float g_g  [Mn*Dn];
__device__             float g_psi[MC];
__device__ __align__(16) float g_h  [Kn*Mn*Dn];
__device__             float g_a  [Mn*Mn*Kn];
__device__ __align__(16) __nv_bfloat16 g_entH[MP*KP];
__device__ __align__(16) __nv_bfloat16 g_entL[MP*KP];
__device__ __align__(16) __nv_bfloat16 g_rkH [Kn*MP*KP];
__device__ __align__(16) __nv_bfloat16 g_rkL [Kn*MP*KP];
__device__ __align__(16) float g_phi[Mn*Mn*Cn*Cn];       // phi[i,j,q,p]
__device__             float g_mbar[2][Mn*Mn*Cn];
__device__             float g_stot[11][MC];

// ---------------- init ----------------
__global__ void k_zero() {
    int t = blockIdx.x * blockDim.x + threadIdx.x;
    if (t < Mn*Mn*Cn) g_mbar[0][t] = 0.f;
    if (t < 11*MC)    (&g_stot[0][0])[t] = 0.f;
    if (t < Kn*MP*KP) {
        int r = (t / KP) % MP, c = t % KP;
        if (r >= MC || c >= Dn) {
            g_rkH[t] = __float2bfloat16(0.f);
            g_rkL[t] = __float2bfloat16(0.f);
        }
    }
}

// ---------------- f = tanh(fmc_in @ W + b) ----------------
__global__ void k_f(const float* __restrict__ fin, const float* __restrict__ W,
                    const float* __restrict__ b) {
    __shared__ float s[4*3*Dn];
    int m0 = blockIdx.x * 4;
    for (int t = threadIdx.x; t < 4*3*Dn; t += 300) s[t] = fin[m0*3*Dn + t];
    __syncthreads();
    int d = threadIdx.x;
    float bb = b[d];
    float a0 = bb, a1 = bb, a2 = bb, a3 = bb;
    for (int k = 0; k < 3*Dn; ++k) {
        float w = W[k*Dn + d];
        a0 = fmaf(s[k],        w, a0);
        a1 = fmaf(s[900 + k],  w, a1);
        a2 = fmaf(s[1800 + k], w, a2);
        a3 = fmaf(s[2700 + k], w, a3);
    }
    g_f[(m0+0)*Dn + d] = tanhf(a0);
    g_f[(m0+1)*Dn + d] = tanhf(a1);
    g_f[(m0+2)*Dn + d] = tanhf(a2);
    g_f[(m0+3)*Dn + d] = tanhf(a3);
}

// ---------------- g[m,d] = dot(f[m,:], B[d,:]) ----------------
__global__ void k_g(const float* __restrict__ Bm) {
    int m = blockIdx.x;
    int w = threadIdx.x >> 5, lane = threadIdx.x & 31;
    int d = blockIdx.y * 4 + w;
    if (d >= Dn) return;
    float acc = 0.f;
    for (int e = lane; e < Dn; e += 32)
        acc = fmaf(g_f[m*Dn + e], Bm[d*Dn + e], acc);
    #pragma unroll
    for (int o = 16; o; o >>= 1) acc += __shfl_down_sync(0xffffffffu, acc, o);
    if (!lane) g_g[m*Dn + d] = acc;
}

// ---------------- psi ----------------
__global__ void k_psi(const float* __restrict__ ent) {
    int m = blockIdx.x;
    int c = threadIdx.x >> 5, lane = threadIdx.x & 31;
    if (c >= Cn) return;
    float acc = 0.f;
    const float* er = ent + (m*Cn + c)*Dn;
    const float* gr = g_g + m*Dn;
    for (int d = lane; d < Dn; d += 32) acc = fmaf(er[d], gr[d], acc);
    #pragma unroll
    for (int o = 16; o; o >>= 1) acc += __shfl_down_sync(0xffffffffu, acc, o);
    if (!lane) g_psi[m*Cn + c] = acc;
}

// ---------------- h ----------------
__global__ void k_h(const float* __restrict__ Dm) {
    __shared__ float sf[4*Dn];
    int i0 = blockIdx.x * 4, k = blockIdx.y;
    for (int t = threadIdx.x; t < 4*Dn; t += 300) sf[t] = g_f[i0*Dn + t];
    __syncthreads();
    int e = threadIdx.x;
    const float* Dk = Dm + (size_t)k*Dn*Dn;
    float a0=0,a1=0,a2=0,a3=0;
    for (int d = 0; d < Dn; ++d) {
        float w = Dk[d*Dn + e];
        a0 = fmaf(sf[d],       w, a0);
        a1 = fmaf(sf[300 + d], w, a1);
        a2 = fmaf(sf[600 + d], w, a2);
        a3 = fmaf(sf[900 + d], w, a3);
    }
    g_h[(k*Mn + i0+0)*Dn + e] = a0;
    g_h[(k*Mn + i0+1)*Dn + e] = a1;
    g_h[(k*Mn + i0+2)*Dn + e] = a2;
    g_h[(k*Mn + i0+3)*Dn + e] = a3;
}

// ---------------- a[i,j,:] ----------------
__global__ void k_a2() {
    __shared__ float sh[Kn][Dn];
    int i = blockIdx.x;
    for (int t = threadIdx.x; t < Kn*Dn; t += 320) {
        int k = t / Dn, e = t - k*Dn;
        sh[k][e] = g_h[(k*Mn + i)*Dn + e];
    }
    __syncthreads();
    int w = threadIdx.x >> 5, lane = threadIdx.x & 31;
    for (int j = w; j < Mn; j += 10) {
        float fr[10];
        #pragma unroll
        for (int r = 0; r < 10; ++r) {
            int e = lane + 32*r;
            fr[r] = (e < Dn) ? g_f[j*Dn + e] : 0.f;
        }
        float sv[3];
        #pragma unroll
        for (int k = 0; k < 3; ++k) {
            float acc = 0.f;
            #pragma unroll
            for (int r = 0; r < 10; ++r) {
                int e = lane + 32*r;
                if (e < Dn) acc = fmaf(fr[r], sh[k][e], acc);
            }
            #pragma unroll
            for (int o = 16; o; o >>= 1) acc += __shfl_xor_sync(0xffffffffu, acc, o);
            sv[k] = acc * (1.0f/17.320508075688772f);
        }
        if (!lane) {
            float mx = fmaxf(sv[0], fmaxf(sv[1], sv[2]));
            float e0 = expf(sv[0]-mx), e1 = expf(sv[1]-mx), e2 = expf(sv[2]-mx);
            float inv = 1.0f / (e0+e1+e2);
            int base = (i*Mn + j)*Kn;
            g_a[base+0] = e0*inv; g_a[base+1] = e1*inv; g_a[base+2] = e2*inv;
        }
    }
}

// ---------------- rk_k = ent_flat @ R_k -> bf16 hi/lo ----------------
__global__ void k_rk(const float* __restrict__ ent, const float* __restrict__ R) {
    const int BM = 64, BN = 64, BK = 8;
    int kk   = blockIdx.z;
    int row0 = blockIdx.y * BM;
    int col0 = blockIdx.x * BN;
    const float* A  = ent;
    const float* Bm = R + (size_t)kk*Dn*Dn;
    __shared__ __align__(16) float As[BK][BM];
    __shared__ __align__(16) float Bs[BK][BN+4];
    int tid = threadIdx.x;
    int tn = tid & 15, tm = tid >> 4;
    float acc[4][4] = {};
    for (int d0 = 0; d0 < Dn; d0 += BK) {
        #pragma unroll
        for (int l = 0; l < 2; ++l) {
            int idx = tid + l*256;
            int mm = idx >> 3, dk = idx & 7;
            int gr = row0 + mm, gd = d0 + dk;
            As[dk][mm] = (gr < MC && gd < Dn) ? A[gr*Dn + gd] : 0.f;
        }
        #pragma unroll
        for (int l = 0; l < 2; ++l) {
            int idx = tid + l*256;
            int dk = idx >> 6, ee = idx & 63;
            int gd = d0 + dk, ge = col0 + ee;
            Bs[dk][ee] = (gd < Dn && ge < Dn) ? Bm[gd*Dn + ge] : 0.f;
        }
        __syncthreads();
        #pragma unroll
        for (int dk = 0; dk < BK; ++dk) {
            float4 ra = *(const float4*)&As[dk][tm*4];
            float4 rb = *(const float4*)&Bs[dk][tn*4];
            float rav[4] = {ra.x, ra.y, ra.z, ra.w};
            float rbv[4] = {rb.x, rb.y, rb.z, rb.w};
            #pragma unroll
            for (int x = 0; x < 4; ++x)
                #pragma unroll
                for (int y = 0; y < 4; ++y)
                    acc[x][y] = fmaf(rav[x], rbv[y], acc[x][y]);
        }
        __syncthreads();
    }
    #pragma unroll
    for (int x = 0; x < 4; ++x) {
        int gr = row0 + tm*4 + x;
        if (gr < MC)
            #pragma unroll
            for (int y = 0; y < 4; ++y) {
                int ge = col0 + tn*4 + y;
                if (ge < Dn) {
                    float v = acc[x][y];
                    __nv_bfloat16 h = __float2bfloat16(v);
                    __nv_bfloat16 l = __float2bfloat16(v - __bfloat162float(h));
                    size_t o = (size_t)kk*MP*KP + (size_t)gr*KP + ge;
                    g_rkH[o] = h; g_rkL[o] = l;
                }
            }
    }
}

// ---------------- split ent -> bf16 hi/lo ----------------
__global__ void k_split(const float* __restrict__ ent) {
    int t = blockIdx.x * 256 + threadIdx.x;
    if (t >= MP*KP) return;
    int row = t / KP, col = t - row*KP;
    float v = (row < MC && col < Dn) ? ent[row*Dn + col] : 0.f;
    __nv_bfloat16 h = __float2bfloat16(v);
    __nv_bfloat16 l = __float2bfloat16(v - __bfloat162float(h));
    g_entH[t] = h; g_entL[t] = l;
}

// ---------------- tensor-core phi ----------------
__device__ __forceinline__ void mma16816(float* c, const uint32_t* a, const uint32_t* b) {
    asm volatile("mma.sync.aligned.m16n8k16.row.col.f32.bf16.bf16.f32 "
        "{%0,%1,%2,%3}, {%4,%5,%6,%7}, {%8,%9}, {%0,%1,%2,%3};"
        : "+f"(c[0]), "+f"(c[1]), "+f"(c[2]), "+f"(c[3])
        : "r"(a[0]), "r"(a[1]), "r"(a[2]), "r"(a[3]), "r"(b[0]), "r"(b[1]));
}
__device__ __forceinline__ void ldsm4(uint32_t* r, uint32_t addr) {
    asm volatile("ldmatrix.sync.aligned.m8n8.x4.shared.b16 {%0,%1,%2,%3}, [%4];"
        : "=r"(r[0]), "=r"(r[1]), "=r"(r[2]), "=r"(r[3]) : "r"(addr));
}
__device__ __forceinline__ uint32_t su32(const void* p) {
    uint32_t a;
    asm("{ .reg .u64 t; cvta.to.shared.u64 t, %1; cvt.u32.u64 %0, t; }" : "=r"(a) : "l"(p));
    return a;
}

// CTA 128(m) x 96(n), 384 threads (12 warps 4x3), warp tile 32x32, plane-inner.
// smem bf16 rows of 72 (144B): A: 6 subtiles (pl*2+hl) x 128 rows; B: 2 (hl) x 96 rows.
#define ROWW 72
#define A_SUB (128*ROWW)          // 9216 bf16
#define B_BASE (6*A_SUB)          // 55296
#define B_SUB (96*ROWW)           // 6912
#define GSM_TOT (B_BASE + 2*B_SUB)   // 69120 bf16 = 138240 B
extern __shared__ __nv_bfloat16 smg[];
__global__ __launch_bounds__(384, 1) void k_gemm() {
    __shared__ float s_a[6][5][3];
    int tid = threadIdx.x, lane = tid & 31, wid = tid >> 5;
    int m0 = blockIdx.y * 128, n0 = blockIdx.x * 96;
    int jb = m0 / 30, ib = n0 / 30;
    int wm = (wid & 3) * 32, wn = (wid >> 2) * 32;
    uint32_t sb = su32(smg);

    if (tid < 90) {
        int jl = tid / 15, rem = tid % 15, il = rem / 3, k = rem % 3;
        int jj = jb + jl, ii = ib + il;
        s_a[jl][il][k] = (jj < Mn && ii < Mn) ? g_a[(ii*Mn + jj)*Kn + k] : 0.f;
    }

    const uint4* AH = (const uint4*)g_rkH;
    const uint4* AL = (const uint4*)g_rkL;
    const uint4* BH = (const uint4*)g_entH;
    const uint4* BL = (const uint4*)g_entL;

    // ldmatrix per-lane addresses
    int g4 = lane >> 3, rin = lane & 7;
    int aRow = wm + ((g4 & 1) << 3) + rin, aK = (g4 >> 1) << 3;
    int bRow = wn + ((g4 >> 1) << 3) + rin, bK = (g4 & 1) << 3;
    // base byte addresses (per mi / nb / pl / hl), k chunk added later
    uint32_t aAd[3][2][2], bAd[2][2];
    #pragma unroll
    for (int pl = 0; pl < 3; ++pl)
        #pragma unroll
        for (int hl = 0; hl < 2; ++hl)
            #pragma unroll
            for (int mi = 0; mi < 2; ++mi)
                aAd[pl][hl][mi] = sb + (uint32_t)(((pl*2 + hl)*128 + aRow + mi*16)*ROWW + aK) * 2u;
    #pragma unroll
    for (int hl = 0; hl < 2; ++hl)
        #pragma unroll
        for (int nb = 0; nb < 2; ++nb)
            bAd[hl][nb] = sb + (uint32_t)(B_BASE + hl*B_SUB + (bRow + nb*16)*ROWW + bK) * 2u;

    float accG[3][2][4][4];
    #pragma unroll
    for (int pl = 0; pl < 3; ++pl)
        #pragma unroll
        for (int mi = 0; mi < 2; ++mi)
            #pragma unroll
            for (int ni = 0; ni < 4; ++ni)
                #pragma unroll
                for (int c = 0; c < 4; ++c) accG[pl][mi][ni][c] = 0.f;

    for (int kc = 0; kc < 5; ++kc) {
        __syncthreads();
        // stage 7680 uint4: A 6x128x8 (1024 per subtile), B 2x96x8 (768 per half)
        #pragma unroll
        for (int l = 0; l < 20; ++l) {
            int u = tid + l*384;
            uint4 v; int dst;
            if (u < 6144) {
                int sub = u >> 10, w2 = u & 1023;
                int r = w2 >> 3, c = w2 & 7;
                int pl = sub >> 1;
                size_t gi = (size_t)pl*(MP*R4U) + (size_t)(m0 + r)*R4U + kc*8 + c;
                v = (sub & 1) ? AL[gi] : AH[gi];
                dst = (sub*128 + r)*ROWW + c*8;
            } else {
                int w2 = u - 6144;              // 0..1535
                int hl = (w2 >= 768) ? 1 : 0;   // FIX: 768 uint4 per half (not power of two)
                int w3 = w2 - hl*768;
                int r = w3 >> 3, c = w3 & 7;
                size_t gi = (size_t)(n0 + r)*R4U + kc*8 + c;
                v = hl ? BL[gi] : BH[gi];
                dst = B_BASE + hl*B_SUB + r*ROWW + c*8;
            }
            *(uint4*)&smg[dst] = v;
        }
        __syncthreads();
        #pragma unroll
        for (int ks = 0; ks < 4; ++ks) {
            uint32_t ko = (uint32_t)(ks * 32);   // ks*16 bf16 in bytes
            uint32_t bf[2][2][4];
            ldsm4(bf[0][0], bAd[0][0] + ko);
            ldsm4(bf[0][1], bAd[0][1] + ko);
            ldsm4(bf[1][0], bAd[1][0] + ko);
            ldsm4(bf[1][1], bAd[1][1] + ko);
            #pragma unroll
            for (int pl = 0; pl < 3; ++pl) {
                uint32_t ah[2][4], al[2][4];
                ldsm4(ah[0], aAd[pl][0][0] + ko);
                ldsm4(ah[1], aAd[pl][0][1] + ko);
                ldsm4(al[0], aAd[pl][1][0] + ko);
                ldsm4(al[1], aAd[pl][1][1] + ko);
                #pragma unroll
                for (int mi = 0; mi < 2; ++mi)
                    #pragma unroll
                    for (int ni = 0; ni < 4; ++ni) {
                        uint32_t bpair_h[2] = { bf[0][ni >> 1][(ni & 1)*2], bf[0][ni >> 1][(ni & 1)*2 + 1] };
                        uint32_t bpair_l[2] = { bf[1][ni >> 1][(ni & 1)*2], bf[1][ni >> 1][(ni & 1)*2 + 1] };
                        mma16816(accG[pl][mi][ni], ah[mi], bpair_h);
                        mma16816(accG[pl][mi][ni], al[mi], bpair_h);
                        mma16816(accG[pl][mi][ni], ah[mi], bpair_l);
                    }
            }
        }
    }
    // epilogue: fold planes with a-weights, write phi[i,j,q,p]
    int fr = lane >> 2, fc = (lane & 3) * 2;
    #pragma unroll
    for (int mi = 0; mi < 2; ++mi) {
        #pragma unroll
        for (int ni = 0; ni < 4; ++ni) {
            #pragma unroll
            for (int c = 0; c < 4; ++c) {
                int m = m0 + wm + mi*16 + fr + ((c >> 1) << 3);
                int n = n0 + wn + ni*8 + fc + (c & 1);
                if (m < MC && n < MC) {
                    int j = m / 30, q = m - j*30;
                    int i = n / 30, p = n - i*30;
                    const float* av = s_a[j - jb][i - ib];
                    float v = av[0]*accG[0][mi][ni][c]
                            + av[1]*accG[1][mi][ni][c]
                            + av[2]*accG[2][mi][ni][c];
                    g_phi[((i*Mn + j)*Cn + q)*Cn + p] = v;
                }
            }
        }
    }
}

// ---------------- LBP iteration: barrier-light ----------------
__global__ void k_lbp(int t) {
    int i  = blockIdx.y;
    int jt = blockIdx.x;
    int src = t & 1;
    const float* mbold = g_mbar[src];
    float*       mbnew = g_mbar[src ^ 1];
    const float* stot  = g_stot[t];
    float*       stotn = g_stot[t+1];
    __shared__ float base0[Cn];
    __shared__ float smv[10][32];
    int tx = threadIdx.x & 31, ty = threadIdx.x >> 5;   // ty = q (30 warps)
    if (threadIdx.x < Cn)
        base0[threadIdx.x] = g_psi[i*Cn + threadIdx.x] + stot[i*Cn + threadIdx.x];
    __syncthreads();
    // phase 1: each q-warp streams all 10 j's independently (no barriers)
    #pragma unroll
    for (int jj = 0; jj < 10; ++jj) {
        int j = jt*10 + jj;
        float v = -1e30f;
        if (tx < Cn)
            v = base0[tx] - mbold[(j*Mn + i)*Cn + tx]
              + g_phi[((i*Mn + j)*Cn + ty)*Cn + tx];
        #pragma unroll
        for (int o = 16; o; o >>= 1) v = fmaxf(v, __shfl_down_sync(0xffffffffu, v, o));
        if (tx == 0) smv[jj][ty] = fmaxf(0.f, v);
    }
    __syncthreads();
    // phase 2: warps 0..9 each finish one j
    if (ty < 10) {
        int j = jt*10 + ty;
        float mv = (tx < Cn) ? smv[ty][tx] : -1e30f;
        float mx = mv;
        #pragma unroll
        for (int o = 16; o; o >>= 1) mx = fmaxf(mx, __shfl_xor_sync(0xffffffffu, mx, o));
        float ex = (tx < Cn) ? expf(mv - mx) : 0.f;
        float s = ex;
        #pragma unroll
        for (int o = 16; o; o >>= 1) s += __shfl_xor_sync(0xffffffffu, s, o);
        if (tx < Cn) {
            float soft = ex / s;
            float oldv = mbold[(i*Mn + j)*Cn + tx];
            float nv = logf(0.5f*expf(oldv) + 0.5f*soft);
            mbnew[(i*Mn + j)*Cn + tx] = nv;
            atomicAdd(&stotn[j*Cn + tx], nv);
        }
    }
}

// ---------------- final ----------------
__global__ void k_fin(float* __restrict__ out) {
    int i = blockIdx.x, q = threadIdx.x;
    const float* mb = g_mbar[0];
    float u = -1e30f;
    if (q < Cn)
        u = g_psi[i*Cn + q] + g_stot[10][i*Cn + q] - mb[(i*Mn + i)*Cn + q];
    float mx = u;
    #pragma unroll
    for (int o = 16; o; o >>= 1) mx = fmaxf(mx, __shfl_xor_sync(0xffffffffu, mx, o));
    float ex = (q < Cn) ? expf(u - mx) : 0.f;
    float s = ex;
    #pragma unroll
    for (int o = 16; o; o >>= 1) s += __shfl_xor_sync(0xffffffffu, s, o);
    if (q < Cn) out[i*Cn + q] = ex / s;
}

// ---------------- launch (k_rk placed 4th for ncu capture) ----------------
extern "C" void kernel_launch(void* const* d_in, const int* in_sizes, int n_in,
                              void* d_out, int out_size) {
    (void)in_sizes; (void)n_in; (void)out_size;
    const float* ent = (const float*)d_in[0];
    const float* fin = (const float*)d_in[1];
    const float* W   = (const float*)d_in[2];
    const float* b   = (const float*)d_in[3];
    const float* Bm  = (const float*)d_in[4];
    const float* R   = (const float*)d_in[5];
    const float* Dm  = (const float*)d_in[6];
    float* out = (float*)d_out;

    const int GEMM_SHMEM = GSM_TOT * 2;   // 138240 B
    cudaFuncSetAttribute(k_gemm, cudaFuncAttributeMaxDynamicSharedMemorySize, GEMM_SHMEM);

    k_zero<<<(Kn*MP*KP + 255)/256, 256>>>();
    k_f  <<<25, 300>>>(fin, W, b);
    k_h  <<<dim3(25, Kn), 300>>>(Dm);
    k_rk <<<dim3(5, 47, Kn), 256>>>(ent, R);      // 4th launch -> ncu
    k_g  <<<dim3(Mn, 75), 128>>>(Bm);
    k_a2 <<<Mn, 320>>>();
    k_psi<<<Mn, 960>>>(ent);
    k_split<<<(MP*KP + 255)/256, 256>>>(ent);
    k_gemm<<<dim3(32, 24), 384, GEMM_SHMEM>>>();

    for (int t = 0; t < 10; ++t)
        k_lbp<<<dim3(10, Mn), 960>>>(t);
    k_fin<<<Mn, 32>>>(out);
}

// round 12
// speedup vs baseline: 1.9573x; 1.0072x over previous
#include <cuda_runtime.h>
#include <cuda_bf16.h>
#include <math.h>
#include <stdint.h>

#define Mn 100
#define Cn 30
#define Dn 300
#define Kn 3
#define MC 3000
#define MP 3072            // padded GEMM dim
#define KP 320             // padded K
#define R4U 40             // uint4 per padded row (320*2/16)
#define NE 384             // padded e-dim for R^T (4 tiles of 96)

// ---------------- scratch ----------------
__device__ __align__(16) float g_f  [Mn*Dn];
__device__ __align__(16) float g_g  [Mn*Dn];
__device__             float g_psi[MC];
__device__ __align__(16) float g_h  [Kn*Mn*Dn];
__device__             float g_a  [Mn*Mn*Kn];
__device__ __align__(16) __nv_bfloat16 g_entH[MP*KP];
__device__ __align__(16) __nv_bfloat16 g_entL[MP*KP];
__device__ __align__(16) __nv_bfloat16 g_rtH [Kn*NE*KP];   // R^T[k][e][d] hi/lo
__device__ __align__(16) __nv_bfloat16 g_rtL [Kn*NE*KP];
__device__ __align__(16) __nv_bfloat16 g_rkH [Kn*MP*KP];
__device__ __align__(16) __nv_bfloat16 g_rkL [Kn*MP*KP];
__device__ __align__(16) float g_phi[Mn*Mn*Cn*Cn];         // phi[i,j,q,p]
__device__             float g_mbar[2][Mn*Mn*Cn];
__device__             float g_stot[11][MC];

// ---------------- PTX helpers ----------------
__device__ __forceinline__ void mma16816(float* c, const uint32_t* a, const uint32_t* b) {
    asm volatile("mma.sync.aligned.m16n8k16.row.col.f32.bf16.bf16.f32 "
        "{%0,%1,%2,%3}, {%4,%5,%6,%7}, {%8,%9}, {%0,%1,%2,%3};"
        : "+f"(c[0]), "+f"(c[1]), "+f"(c[2]), "+f"(c[3])
        : "r"(a[0]), "r"(a[1]), "r"(a[2]), "r"(a[3]), "r"(b[0]), "r"(b[1]));
}
__device__ __forceinline__ void ldsm4(uint32_t* r, uint32_t addr) {
    asm volatile("ldmatrix.sync.aligned.m8n8.x4.shared.b16 {%0,%1,%2,%3}, [%4];"
        : "=r"(r[0]), "=r"(r[1]), "=r"(r[2]), "=r"(r[3]) : "r"(addr));
}
__device__ __forceinline__ uint32_t su32(const void* p) {
    uint32_t a;
    asm("{ .reg .u64 t; cvta.to.shared.u64 t, %1; cvt.u32.u64 %0, t; }" : "=r"(a) : "l"(p));
    return a;
}
__device__ __forceinline__ void cpasync16(uint32_t dst, const void* src) {
    asm volatile("cp.async.cg.shared.global [%0], [%1], 16;" :: "r"(dst), "l"(src));
}
#define CP_COMMIT() asm volatile("cp.async.commit_group;" ::: "memory")
#define CP_WAIT(n)  asm volatile("cp.async.wait_group %0;" :: "n"(n) : "memory")

// ---------------- init ----------------
__global__ void k_zero() {
    int t = blockIdx.x * blockDim.x + threadIdx.x;
    if (t < Mn*Mn*Cn) g_mbar[0][t] = 0.f;
    if (t < 11*MC)    (&g_stot[0][0])[t] = 0.f;
}

// ---------------- f = tanh(fmc_in @ W + b) ----------------
__global__ void k_f(const float* __restrict__ fin, const float* __restrict__ W,
                    const float* __restrict__ b) {
    __shared__ float s[4*3*Dn];
    int m0 = blockIdx.x * 4;
    for (int t = threadIdx.x; t < 4*3*Dn; t += 300) s[t] = fin[m0*3*Dn + t];
    __syncthreads();
    int d = threadIdx.x;
    float bb = b[d];
    float a0 = bb, a1 = bb, a2 = bb, a3 = bb;
    for (int k = 0; k < 3*Dn; ++k) {
        float w = W[k*Dn + d];
        a0 = fmaf(s[k],        w, a0);
        a1 = fmaf(s[900 + k],  w, a1);
        a2 = fmaf(s[1800 + k], w, a2);
        a3 = fmaf(s[2700 + k], w, a3);
    }
    g_f[(m0+0)*Dn + d] = tanhf(a0);
    g_f[(m0+1)*Dn + d] = tanhf(a1);
    g_f[(m0+2)*Dn + d] = tanhf(a2);
    g_f[(m0+3)*Dn + d] = tanhf(a3);
}

// ---------------- g[m,d] = dot(f[m,:], B[d,:]) ----------------
__global__ void k_g(const float* __restrict__ Bm) {
    int m = blockIdx.x;
    int w = threadIdx.x >> 5, lane = threadIdx.x & 31;
    int d = blockIdx.y * 4 + w;
    if (d >= Dn) return;
    float acc = 0.f;
    for (int e = lane; e < Dn; e += 32)
        acc = fmaf(g_f[m*Dn + e], Bm[d*Dn + e], acc);
    #pragma unroll
    for (int o = 16; o; o >>= 1) acc += __shfl_down_sync(0xffffffffu, acc, o);
    if (!lane) g_g[m*Dn + d] = acc;
}

// ---------------- psi ----------------
__global__ void k_psi(const float* __restrict__ ent) {
    int m = blockIdx.x;
    int c = threadIdx.x >> 5, lane = threadIdx.x & 31;
    if (c >= Cn) return;
    float acc = 0.f;
    const float* er = ent + (m*Cn + c)*Dn;
    const float* gr = g_g + m*Dn;
    for (int d = lane; d < Dn; d += 32) acc = fmaf(er[d], gr[d], acc);
    #pragma unroll
    for (int o = 16; o; o >>= 1) acc += __shfl_down_sync(0xffffffffu, acc, o);
    if (!lane) g_psi[m*Cn + c] = acc;
}

// ---------------- h ----------------
__global__ void k_h(const float* __restrict__ Dm) {
    __shared__ float sf[4*Dn];
    int i0 = blockIdx.x * 4, k = blockIdx.y;
    for (int t = threadIdx.x; t < 4*Dn; t += 300) sf[t] = g_f[i0*Dn + t];
    __syncthreads();
    int e = threadIdx.x;
    const float* Dk = Dm + (size_t)k*Dn*Dn;
    float a0=0,a1=0,a2=0,a3=0;
    for (int d = 0; d < Dn; ++d) {
        float w = Dk[d*Dn + e];
        a0 = fmaf(sf[d],       w, a0);
        a1 = fmaf(sf[300 + d], w, a1);
        a2 = fmaf(sf[600 + d], w, a2);
        a3 = fmaf(sf[900 + d], w, a3);
    }
    g_h[(k*Mn + i0+0)*Dn + e] = a0;
    g_h[(k*Mn + i0+1)*Dn + e] = a1;
    g_h[(k*Mn + i0+2)*Dn + e] = a2;
    g_h[(k*Mn + i0+3)*Dn + e] = a3;
}

// ---------------- a[i,j,:] ----------------
__global__ void k_a2() {
    __shared__ float sh[Kn][Dn];
    int i = blockIdx.x;
    for (int t = threadIdx.x; t < Kn*Dn; t += 320) {
        int k = t / Dn, e = t - k*Dn;
        sh[k][e] = g_h[(k*Mn + i)*Dn + e];
    }
    __syncthreads();
    int w = threadIdx.x >> 5, lane = threadIdx.x & 31;
    for (int j = w; j < Mn; j += 10) {
        float fr[10];
        #pragma unroll
        for (int r = 0; r < 10; ++r) {
            int e = lane + 32*r;
            fr[r] = (e < Dn) ? g_f[j*Dn + e] : 0.f;
        }
        float sv[3];
        #pragma unroll
        for (int k = 0; k < 3; ++k) {
            float acc = 0.f;
            #pragma unroll
            for (int r = 0; r < 10; ++r) {
                int e = lane + 32*r;
                if (e < Dn) acc = fmaf(fr[r], sh[k][e], acc);
            }
            #pragma unroll
            for (int o = 16; o; o >>= 1) acc += __shfl_xor_sync(0xffffffffu, acc, o);
            sv[k] = acc * (1.0f/17.320508075688772f);
        }
        if (!lane) {
            float mx = fmaxf(sv[0], fmaxf(sv[1], sv[2]));
            float e0 = expf(sv[0]-mx), e1 = expf(sv[1]-mx), e2 = expf(sv[2]-mx);
            float inv = 1.0f / (e0+e1+e2);
            int base = (i*Mn + j)*Kn;
            g_a[base+0] = e0*inv; g_a[base+1] = e1*inv; g_a[base+2] = e2*inv;
        }
    }
}

// ---------------- split ent -> bf16 hi/lo ----------------
__global__ void k_split(const float* __restrict__ ent) {
    int t = blockIdx.x * 256 + threadIdx.x;
    if (t >= MP*KP) return;
    int row = t / KP, col = t - row*KP;
    float v = (row < MC && col < Dn) ? ent[row*Dn + col] : 0.f;
    __nv_bfloat16 h = __float2bfloat16(v);
    __nv_bfloat16 l = __float2bfloat16(v - __bfloat162float(h));
    g_entH[t] = h; g_entL[t] = l;
}

// ---------------- split R^T -> bf16 hi/lo padded [3][384][320] ----------------
__global__ void k_splitR(const float* __restrict__ R) {
    int t = blockIdx.x * 256 + threadIdx.x;
    if (t >= Kn*NE*KP) return;
    int k = t / (NE*KP), r = t - k*(NE*KP);
    int e = r / KP, d = r - e*KP;
    float v = (e < Dn && d < Dn) ? R[(size_t)k*Dn*Dn + (size_t)d*Dn + e] : 0.f;
    __nv_bfloat16 h = __float2bfloat16(v);
    __nv_bfloat16 l = __float2bfloat16(v - __bfloat162float(h));
    g_rtH[t] = h; g_rtL[t] = l;
}

// ---------------- rk via tensor cores: rk[k] = ent @ R_k (bf16 hi/lo 3-pass) ----------------
// CTA 128(m) x 96(e), 384 threads (12 warps 4x3), warp 32x32; BK=64, 5 chunks, single buffer.
// smem bf16 rows of 72: Ah 128, Al 128, Bh 96, Bl 96 = 32256 bf16 = 64512 B
#define RK_AH 0
#define RK_AL 9216
#define RK_BH 18432
#define RK_BL 25344
extern __shared__ __nv_bfloat16 smr[];
__global__ __launch_bounds__(384, 2) void k_rk_mma() {
    int tid = threadIdx.x, lane = tid & 31, wid = tid >> 5;
    int kk = blockIdx.z;
    int m0 = blockIdx.y * 128, n0 = blockIdx.x * 96;
    int wm = (wid & 3) * 32, wn = (wid >> 2) * 32;
    uint32_t sb = su32(smr);

    const uint4* AH = (const uint4*)g_entH;
    const uint4* AL = (const uint4*)g_entL;
    const uint4* BH = (const uint4*)g_rtH + (size_t)kk*(NE*R4U);
    const uint4* BL = (const uint4*)g_rtL + (size_t)kk*(NE*R4U);

    int g4 = lane >> 3, rin = lane & 7;
    int aRow = wm + ((g4 & 1) << 3) + rin, aK = (g4 >> 1) << 3;
    int bRow = wn + ((g4 >> 1) << 3) + rin, bK = (g4 & 1) << 3;
    uint32_t aAd[2][2], bAd[2][2];
    #pragma unroll
    for (int hl = 0; hl < 2; ++hl) {
        #pragma unroll
        for (int mi = 0; mi < 2; ++mi)
            aAd[hl][mi] = sb + (uint32_t)((hl ? RK_AL : RK_AH) + (aRow + mi*16)*72 + aK) * 2u;
        #pragma unroll
        for (int nb = 0; nb < 2; ++nb)
            bAd[hl][nb] = sb + (uint32_t)((hl ? RK_BL : RK_BH) + (bRow + nb*16)*72 + bK) * 2u;
    }

    float acc[2][4][4];
    #pragma unroll
    for (int mi = 0; mi < 2; ++mi)
        #pragma unroll
        for (int ni = 0; ni < 4; ++ni)
            #pragma unroll
            for (int c = 0; c < 4; ++c) acc[mi][ni][c] = 0.f;

    for (int kc = 0; kc < 5; ++kc) {
        __syncthreads();
        // stage 3584 uint4: A hi/lo 2x1024, B hi/lo 2x768
        #pragma unroll
        for (int l = 0; l < 10; ++l) {
            int u = tid + l*384;
            if (u >= 3584) break;
            uint4 v; int dst;
            if (u < 2048) {
                int hl = u >> 10, w2 = u & 1023;
                int r = w2 >> 3, c = w2 & 7;
                size_t gi = (size_t)(m0 + r)*R4U + kc*8 + c;
                v = hl ? AL[gi] : AH[gi];
                dst = (hl ? RK_AL : RK_AH) + r*72 + c*8;
            } else {
                int w2 = u - 2048;              // 0..1535
                int hl = (w2 >= 768) ? 1 : 0;
                int w3 = w2 - hl*768;
                int r = w3 >> 3, c = w3 & 7;
                size_t gi = (size_t)(n0 + r)*R4U + kc*8 + c;
                v = hl ? BL[gi] : BH[gi];
                dst = (hl ? RK_BL : RK_BH) + r*72 + c*8;
            }
            *(uint4*)&smr[dst] = v;
        }
        __syncthreads();
        #pragma unroll
        for (int ks = 0; ks < 4; ++ks) {
            uint32_t ko = (uint32_t)(ks * 32);
            uint32_t bh[2][4], bl[2][4], ah[2][4], al[2][4];
            ldsm4(bh[0], bAd[0][0] + ko);
            ldsm4(bh[1], bAd[0][1] + ko);
            ldsm4(bl[0], bAd[1][0] + ko);
            ldsm4(bl[1], bAd[1][1] + ko);
            ldsm4(ah[0], aAd[0][0] + ko);
            ldsm4(ah[1], aAd[0][1] + ko);
            ldsm4(al[0], aAd[1][0] + ko);
            ldsm4(al[1], aAd[1][1] + ko);
            #pragma unroll
            for (int mi = 0; mi < 2; ++mi)
                #pragma unroll
                for (int ni = 0; ni < 4; ++ni) {
                    uint32_t bph[2] = { bh[ni >> 1][(ni & 1)*2], bh[ni >> 1][(ni & 1)*2 + 1] };
                    uint32_t bpl[2] = { bl[ni >> 1][(ni & 1)*2], bl[ni >> 1][(ni & 1)*2 + 1] };
                    mma16816(acc[mi][ni], ah[mi], bph);
                    mma16816(acc[mi][ni], al[mi], bph);
                    mma16816(acc[mi][ni], ah[mi], bpl);
                }
        }
    }
    int fr = lane >> 2, fc = (lane & 3) * 2;
    #pragma unroll
    for (int mi = 0; mi < 2; ++mi)
        #pragma unroll
        for (int ni = 0; ni < 4; ++ni)
            #pragma unroll
            for (int c = 0; c < 4; ++c) {
                int m = m0 + wm + mi*16 + fr + ((c >> 1) << 3);
                int n = n0 + wn + ni*8 + fc + (c & 1);
                if (n < KP) {
                    float v = acc[mi][ni][c];
                    __nv_bfloat16 h = __float2bfloat16(v);
                    __nv_bfloat16 l = __float2bfloat16(v - __bfloat162float(h));
                    size_t o = (size_t)kk*MP*KP + (size_t)m*KP + n;
                    g_rkH[o] = h; g_rkL[o] = l;
                }
            }
}

// ---------------- tensor-core phi: cp.async double-buffered ----------------
// CTA 128(m) x 96(n), 384 threads, warp 32x32, plane-inner accumulators.
// BK=32 (10 chunks). Per buffer (bf16): A 6x128x40=30720, B 2x96x40=7680 -> 38400 (76800 B).
#define ROW2 40
#define A2SUB (128*ROW2)            // 5120
#define B2OFF (6*A2SUB)             // 30720
#define B2SUB (96*ROW2)             // 3840
#define BUF2  (B2OFF + 2*B2SUB)     // 38400 bf16 = 76800 B
extern __shared__ __nv_bfloat16 smg[];
__global__ __launch_bounds__(384, 1) void k_gemm() {
    __shared__ float s_a[6][5][3];
    int tid = threadIdx.x, lane = tid & 31, wid = tid >> 5;
    int m0 = blockIdx.y * 128, n0 = blockIdx.x * 96;
    int jb = m0 / 30, ib = n0 / 30;
    int wm = (wid & 3) * 32, wn = (wid >> 2) * 32;
    uint32_t sb = su32(smg);

    if (tid < 90) {
        int jl = tid / 15, rem = tid % 15, il = rem / 3, k = rem % 3;
        int jj = jb + jl, ii = ib + il;
        s_a[jl][il][k] = (jj < Mn && ii < Mn) ? g_a[(ii*Mn + jj)*Kn + k] : 0.f;
    }

    const uint4* AH = (const uint4*)g_rkH;
    const uint4* AL = (const uint4*)g_rkL;
    const uint4* BH = (const uint4*)g_entH;
    const uint4* BL = (const uint4*)g_entL;

    int g4 = lane >> 3, rin = lane & 7;
    int aRow = wm + ((g4 & 1) << 3) + rin, aK = (g4 >> 1) << 3;
    int bRow = wn + ((g4 >> 1) << 3) + rin, bK = (g4 & 1) << 3;
    uint32_t aAd[3][2][2], bAd[2][2];
    #pragma unroll
    for (int pl = 0; pl < 3; ++pl)
        #pragma unroll
        for (int hl = 0; hl < 2; ++hl)
            #pragma unroll
            for (int mi = 0; mi < 2; ++mi)
                aAd[pl][hl][mi] = sb + (uint32_t)((pl*2 + hl)*A2SUB + (aRow + mi*16)*ROW2 + aK) * 2u;
    #pragma unroll
    for (int hl = 0; hl < 2; ++hl)
        #pragma unroll
        for (int nb = 0; nb < 2; ++nb)
            bAd[hl][nb] = sb + (uint32_t)(B2OFF + hl*B2SUB + (bRow + nb*16)*ROW2 + bK) * 2u;

    float accG[3][2][4][4];
    #pragma unroll
    for (int pl = 0; pl < 3; ++pl)
        #pragma unroll
        for (int mi = 0; mi < 2; ++mi)
            #pragma unroll
            for (int ni = 0; ni < 4; ++ni)
                #pragma unroll
                for (int c = 0; c < 4; ++c) accG[pl][mi][ni][c] = 0.f;

    // stage one BK=32 chunk into buffer `bsel` via cp.async (3840 uint4, 10/thread)
    auto stage = [&](int kc, int bsel) {
        uint32_t bufb = sb + (uint32_t)bsel * (BUF2 * 2);
        #pragma unroll
        for (int l = 0; l < 10; ++l) {
            int u = tid + l*384;   // 0..3839 exactly
            const uint4* srcp; int dst;
            if (u < 3072) {
                int sub = u >> 9, w2 = u & 511;
                int r = w2 >> 2, c = w2 & 3;
                int pl = sub >> 1;
                size_t gi = (size_t)pl*(MP*R4U) + (size_t)(m0 + r)*R4U + kc*4 + c;
                srcp = (sub & 1) ? (AL + gi) : (AH + gi);
                dst = sub*A2SUB + r*ROW2 + c*8;
            } else {
                int w2 = u - 3072;              // 0..767
                int hl = (w2 >= 384) ? 1 : 0;
                int w3 = w2 - hl*384;
                int r = w3 >> 2, c = w3 & 3;
                size_t gi = (size_t)(n0 + r)*R4U + kc*4 + c;
                srcp = hl ? (BL + gi) : (BH + gi);
                dst = B2OFF + hl*B2SUB + r*ROW2 + c*8;
            }
            cpasync16(bufb + (uint32_t)dst*2u, srcp);
        }
    };

    stage(0, 0);
    CP_COMMIT();
    for (int kc = 0; kc < 10; ++kc) {
        if (kc < 9) { stage(kc+1, (kc+1) & 1); CP_COMMIT(); }
        if (kc < 9) { CP_WAIT(1); } else { CP_WAIT(0); }
        __syncthreads();
        uint32_t bo = (uint32_t)(kc & 1) * (BUF2 * 2);
        #pragma unroll
        for (int ks = 0; ks < 2; ++ks) {
            uint32_t ko = bo + (uint32_t)(ks * 32);
            uint32_t bf[2][2][4];
            ldsm4(bf[0][0], bAd[0][0] + ko);
            ldsm4(bf[0][1], bAd[0][1] + ko);
            ldsm4(bf[1][0], bAd[1][0] + ko);
            ldsm4(bf[1][1], bAd[1][1] + ko);
            #pragma unroll
            for (int pl = 0; pl < 3; ++pl) {
                uint32_t ah[2][4], al[2][4];
                ldsm4(ah[0], aAd[pl][0][0] + ko);
                ldsm4(ah[1], aAd[pl][0][1] + ko);
                ldsm4(al[0], aAd[pl][1][0] + ko);
                ldsm4(al[1], aAd[pl][1][1] + ko);
                #pragma unroll
                for (int mi = 0; mi < 2; ++mi)
                    #pragma unroll
                    for (int ni = 0; ni < 4; ++ni) {
                        uint32_t bph[2] = { bf[0][ni >> 1][(ni & 1)*2], bf[0][ni >> 1][(ni & 1)*2 + 1] };
                        uint32_t bpl[2] = { bf[1][ni >> 1][(ni & 1)*2], bf[1][ni >> 1][(ni & 1)*2 + 1] };
                        mma16816(accG[pl][mi][ni], ah[mi], bph);
                        mma16816(accG[pl][mi][ni], al[mi], bph);
                        mma16816(accG[pl][mi][ni], ah[mi], bpl);
                    }
            }
        }
        __syncthreads();
    }
    // epilogue: fold planes with a-weights, write phi[i,j,q,p]
    int fr = lane >> 2, fc = (lane & 3) * 2;
    #pragma unroll
    for (int mi = 0; mi < 2; ++mi) {
        #pragma unroll
        for (int ni = 0; ni < 4; ++ni) {
            #pragma unroll
            for (int c = 0; c < 4; ++c) {
                int m = m0 + wm + mi*16 + fr + ((c >> 1) << 3);
                int n = n0 + wn + ni*8 + fc + (c & 1);
                if (m < MC && n < MC) {
                    int j = m / 30, q = m - j*30;
                    int i = n / 30, p = n - i*30;
                    const float* av = s_a[j - jb][i - ib];
                    float v = av[0]*accG[0][mi][ni][c]
                            + av[1]*accG[1][mi][ni][c]
                            + av[2]*accG[2][mi][ni][c];
                    g_phi[((i*Mn + j)*Cn + q)*Cn + p] = v;
                }
            }
        }
    }
}

// ---------------- LBP iteration: barrier-light ----------------
__global__ void k_lbp(int t) {
    int i  = blockIdx.y;
    int jt = blockIdx.x;
    int src = t & 1;
    const float* mbold = g_mbar[src];
    float*       mbnew = g_mbar[src ^ 1];
    const float* stot  = g_stot[t];
    float*       stotn = g_stot[t+1];
    __shared__ float base0[Cn];
    __shared__ float smv[10][32];
    int tx = threadIdx.x & 31, ty = threadIdx.x >> 5;   // ty = q (30 warps)
    if (threadIdx.x < Cn)
        base0[threadIdx.x] = g_psi[i*Cn + threadIdx.x] + stot[i*Cn + threadIdx.x];
    __syncthreads();
    #pragma unroll
    for (int jj = 0; jj < 10; ++jj) {
        int j = jt*10 + jj;
        float v = -1e30f;
        if (tx < Cn)
            v = base0[tx] - mbold[(j*Mn + i)*Cn + tx]
              + g_phi[((i*Mn + j)*Cn + ty)*Cn + tx];
        #pragma unroll
        for (int o = 16; o; o >>= 1) v = fmaxf(v, __shfl_down_sync(0xffffffffu, v, o));
        if (tx == 0) smv[jj][ty] = fmaxf(0.f, v);
    }
    __syncthreads();
    if (ty < 10) {
        int j = jt*10 + ty;
        float mv = (tx < Cn) ? smv[ty][tx] : -1e30f;
        float mx = mv;
        #pragma unroll
        for (int o = 16; o; o >>= 1) mx = fmaxf(mx, __shfl_xor_sync(0xffffffffu, mx, o));
        float ex = (tx < Cn) ? expf(mv - mx) : 0.f;
        float s = ex;
        #pragma unroll
        for (int o = 16; o; o >>= 1) s += __shfl_xor_sync(0xffffffffu, s, o);
        if (tx < Cn) {
            float soft = ex / s;
            float oldv = mbold[(i*Mn + j)*Cn + tx];
            float nv = logf(0.5f*expf(oldv) + 0.5f*soft);
            mbnew[(i*Mn + j)*Cn + tx] = nv;
            atomicAdd(&stotn[j*Cn + tx], nv);
        }
    }
}

// ---------------- final ----------------
__global__ void k_fin(float* __restrict__ out) {
    int i = blockIdx.x, q = threadIdx.x;
    const float* mb = g_mbar[0];
    float u = -1e30f;
    if (q < Cn)
        u = g_psi[i*Cn + q] + g_stot[10][i*Cn + q] - mb[(i*Mn + i)*Cn + q];
    float mx = u;
    #pragma unroll
    for (int o = 16; o; o >>= 1) mx = fmaxf(mx, __shfl_xor_sync(0xffffffffu, mx, o));
    float ex = (q < Cn) ? expf(u - mx) : 0.f;
    float s = ex;
    #pragma unroll
    for (int o = 16; o; o >>= 1) s += __shfl_xor_sync(0xffffffffu, s, o);
    if (q < Cn) out[i*Cn + q] = ex / s;
}

// ---------------- launch (k_rk_mma placed 4th for ncu capture) ----------------
extern "C" void kernel_launch(void* const* d_in, const int* in_sizes, int n_in,
                              void* d_out, int out_size) {
    (void)in_sizes; (void)n_in; (void)out_size;
    const float* ent = (const float*)d_in[0];
    const float* fin = (const float*)d_in[1];
    const float* W   = (const float*)d_in[2];
    const float* b   = (const float*)d_in[3];
    const float* Bm  = (const float*)d_in[4];
    const float* R   = (const float*)d_in[5];
    const float* Dm  = (const float*)d_in[6];
    float* out = (float*)d_out;

    const int GEMM_SHMEM = BUF2 * 2 * 2;    // 153600 B
    const int RK_SHMEM   = 32256 * 2;       // 64512 B
    cudaFuncSetAttribute(k_gemm,   cudaFuncAttributeMaxDynamicSharedMemorySize, GEMM_SHMEM);
    cudaFuncSetAttribute(k_rk_mma, cudaFuncAttributeMaxDynamicSharedMemorySize, RK_SHMEM);

    k_zero  <<<(Mn*Mn*Cn + 255)/256, 256>>>();
    k_split <<<(MP*KP + 255)/256, 256>>>(ent);
    k_splitR<<<(Kn*NE*KP + 255)/256, 256>>>(R);
    k_rk_mma<<<dim3(4, 24, Kn), 384, RK_SHMEM>>>();      // 4th launch -> ncu
    k_f  <<<25, 300>>>(fin, W, b);
    k_h  <<<dim3(25, Kn), 300>>>(Dm);
    k_g  <<<dim3(Mn, 75), 128>>>(Bm);
    k_a2 <<<Mn, 320>>>();
    k_psi<<<Mn, 960>>>(ent);
    k_gemm<<<dim3(32, 24), 384, GEMM_SHMEM>>>();

    for (int t = 0; t < 10; ++t)
        k_lbp<<<dim3(10, Mn), 960>>>(t);
    k_fin<<<Mn, 32>>>(out);
}